// round 7
// baseline (speedup 1.0000x reference)
#include <cuda_runtime.h>
#include <cuda_bf16.h>
#include <math.h>
#include <stdint.h>

#define S_LEN 2048
#define D_EMB 1024
#define NHEAD 16
#define DH    64
#define BATCH 2
#define MROWS (BATCH * S_LEN)   // 4096
#define LDK   68

// ---------------- device scratch ----------------
__device__ float g_q[MROWS * D_EMB];
__device__ float g_k[MROWS * D_EMB];
__device__ float g_v[MROWS * D_EMB];
__device__ float g_attn[MROWS * D_EMB];

__device__ __nv_bfloat16 g_xh[MROWS * D_EMB];
__device__ __nv_bfloat16 g_xl[MROWS * D_EMB];
__device__ __nv_bfloat16 g_ah[MROWS * D_EMB];
__device__ __nv_bfloat16 g_al[MROWS * D_EMB];

__device__ __nv_bfloat16 g_wqh[D_EMB * D_EMB];
__device__ __nv_bfloat16 g_wql[D_EMB * D_EMB];
__device__ __nv_bfloat16 g_wkh[D_EMB * D_EMB];
__device__ __nv_bfloat16 g_wkl[D_EMB * D_EMB];
__device__ __nv_bfloat16 g_wvh[D_EMB * D_EMB];
__device__ __nv_bfloat16 g_wvl[D_EMB * D_EMB];
__device__ __nv_bfloat16 g_woh[D_EMB * D_EMB];
__device__ __nv_bfloat16 g_wol[D_EMB * D_EMB];

// ---------------- helpers ----------------
__device__ __forceinline__ uint32_t smem_to_u32(const void* p) {
    uint32_t a;
    asm("{ .reg .u64 t; cvta.to.shared.u64 t, %1; cvt.u32.u64 %0, t; }"
        : "=r"(a) : "l"(p));
    return a;
}

__device__ __forceinline__ void cp16(uint32_t s, const void* g) {
    asm volatile("cp.async.cg.shared.global [%0], [%1], 16;" :: "r"(s), "l"(g));
}
#define CP_COMMIT() asm volatile("cp.async.commit_group;" ::: "memory")
#define CP_WAIT_ALL() asm volatile("cp.async.wait_group 0;" ::: "memory")

#define LDSM_X4(r0, r1, r2, r3, addr) \
    asm volatile("ldmatrix.sync.aligned.m8n8.x4.shared.b16 {%0,%1,%2,%3}, [%4];" \
        : "=r"(r0), "=r"(r1), "=r"(r2), "=r"(r3) : "r"(addr))

#define MMA16816(c, a, b0, b1) \
    asm volatile("mma.sync.aligned.m16n8k16.row.col.f32.bf16.bf16.f32 " \
        "{%0,%1,%2,%3}, {%4,%5,%6,%7}, {%8,%9}, {%0,%1,%2,%3};" \
        : "+f"((c)[0]), "+f"((c)[1]), "+f"((c)[2]), "+f"((c)[3]) \
        : "r"((a)[0]), "r"((a)[1]), "r"((a)[2]), "r"((a)[3]), "r"(b0), "r"(b1))

// FMA-pipe exp (no MUFU): exp(x) = 2^(x*log2e), deg-5 Taylor on [-0.5,0.5].
// Valid for x <= 0 (clamped at -87 -> ~0); handles -inf via the clamp.
__device__ __forceinline__ float fast_exp(float x) {
    x = fmaxf(x, -87.0f);
    float y = fmaf(x, 1.4426950408889634f, 12582912.0f);  // round y0 to int (RNE)
    int   e = __float_as_int(y) - 0x4B400000;             // exact int in low bits
    float i = y - 12582912.0f;
    float f = fmaf(x, 1.4426950408889634f, -i);           // f in [-0.5, 0.5]
    float p =           1.3333558e-3f;
    p = fmaf(p, f, 9.6181291e-3f);
    p = fmaf(p, f, 5.5504109e-2f);
    p = fmaf(p, f, 2.4022651e-1f);
    p = fmaf(p, f, 6.9314718e-1f);
    p = fmaf(p, f, 1.0f);
    return p * __int_as_float((127 + e) << 23);
}

// ---------------------------------------------------------------------------
// split fp32 -> bf16 hi/lo
// ---------------------------------------------------------------------------
__global__ __launch_bounds__(256)
void split_bf16_kernel(const float* __restrict__ in,
                       __nv_bfloat16* __restrict__ hi,
                       __nv_bfloat16* __restrict__ lo, int n4)
{
    int idx = blockIdx.x * 256 + threadIdx.x;
    if (idx >= n4) return;
    float4 v = *(const float4*)(in + (size_t)idx * 4);
    __nv_bfloat16 h0 = __float2bfloat16(v.x);
    __nv_bfloat16 h1 = __float2bfloat16(v.y);
    __nv_bfloat16 h2 = __float2bfloat16(v.z);
    __nv_bfloat16 h3 = __float2bfloat16(v.w);
    __nv_bfloat16 l0 = __float2bfloat16(v.x - __bfloat162float(h0));
    __nv_bfloat16 l1 = __float2bfloat16(v.y - __bfloat162float(h1));
    __nv_bfloat16 l2 = __float2bfloat16(v.z - __bfloat162float(h2));
    __nv_bfloat16 l3 = __float2bfloat16(v.w - __bfloat162float(h3));
    __nv_bfloat162* hp = (__nv_bfloat162*)(hi + (size_t)idx * 4);
    __nv_bfloat162* lp = (__nv_bfloat162*)(lo + (size_t)idx * 4);
    hp[0] = __nv_bfloat162(h0, h1);
    hp[1] = __nv_bfloat162(h2, h3);
    lp[0] = __nv_bfloat162(l0, l1);
    lp[1] = __nv_bfloat162(l2, l3);
}

// ---------------------------------------------------------------------------
// transpose + split:  Wt[n,k] = W[k,n]  (1024x1024)
// ---------------------------------------------------------------------------
__global__ __launch_bounds__(256)
void transpose_split_kernel(const float* __restrict__ W,
                            __nv_bfloat16* __restrict__ th,
                            __nv_bfloat16* __restrict__ tl)
{
    __shared__ float t[32][33];
    const int tx = threadIdx.x, ty = threadIdx.y;  // 32 x 8
    const int n0 = blockIdx.x * 32;
    const int k0 = blockIdx.y * 32;
#pragma unroll
    for (int i = 0; i < 4; i++)
        t[ty + i * 8][tx] = W[(size_t)(k0 + ty + i * 8) * D_EMB + n0 + tx];
    __syncthreads();
#pragma unroll
    for (int i = 0; i < 4; i++) {
        int n = n0 + ty + i * 8;
        int k = k0 + tx;
        float v = t[tx][ty + i * 8];
        __nv_bfloat16 h = __float2bfloat16(v);
        __nv_bfloat16 l = __float2bfloat16(v - __bfloat162float(h));
        th[(size_t)n * D_EMB + k] = h;
        tl[(size_t)n * D_EMB + k] = l;
    }
}

// ---------------------------------------------------------------------------
// mma.sync GEMM: C[4096,1024] = (Ah+Al) @ (Wh+Wl)^T + bias
// ---------------------------------------------------------------------------
#define ROWB      80
#define STAGE_A   (128 * ROWB)
#define STAGE_B   (256 * ROWB)
#define STAGE_TOTAL (2 * STAGE_A + 2 * STAGE_B)
#define GEMM_SMEM (2 * STAGE_TOTAL)

__device__ __forceinline__ void load_stage(
    const __nv_bfloat16* __restrict__ Ah, const __nv_bfloat16* __restrict__ Al,
    const __nv_bfloat16* __restrict__ Bh, const __nv_bfloat16* __restrict__ Bl,
    int rowBase, int colBase, int k0, uint32_t sbase, int tid)
{
#pragma unroll
    for (int i = 0; i < 2; i++) {
        int c = tid * 2 + i;
        int r = c >> 2, kc = c & 3;
        size_t goff = (size_t)(rowBase + r) * D_EMB + k0 + kc * 8;
        uint32_t soff = r * ROWB + kc * 16;
        cp16(sbase + soff, Ah + goff);
        cp16(sbase + STAGE_A + soff, Al + goff);
    }
#pragma unroll
    for (int i = 0; i < 4; i++) {
        int c = tid * 4 + i;
        int r = c >> 2, kc = c & 3;
        size_t goff = (size_t)(colBase + r) * D_EMB + k0 + kc * 8;
        uint32_t soff = r * ROWB + kc * 16;
        cp16(sbase + 2 * STAGE_A + soff, Bh + goff);
        cp16(sbase + 2 * STAGE_A + STAGE_B + soff, Bl + goff);
    }
}

__global__ __launch_bounds__(256, 1)
void mma_gemm_bias_kernel(const __nv_bfloat16* __restrict__ Ah,
                          const __nv_bfloat16* __restrict__ Al,
                          const __nv_bfloat16* __restrict__ Wh,
                          const __nv_bfloat16* __restrict__ Wl,
                          const float* __restrict__ bias,
                          float* __restrict__ C)
{
    extern __shared__ char smem[];
    const uint32_t sbase = smem_to_u32(smem);
    const int tid = threadIdx.x;
    const int wid = tid >> 5;
    const int lid = tid & 31;
    const int wm = wid & 1;
    const int wn = wid >> 1;
    const int rowBase = blockIdx.y * 128;
    const int colBase = blockIdx.x * 256;

    float c[4][8][4];
#pragma unroll
    for (int i = 0; i < 4; i++)
#pragma unroll
        for (int j = 0; j < 8; j++)
#pragma unroll
            for (int q = 0; q < 4; q++) c[i][j][q] = 0.f;

    const uint32_t a_lane = (uint32_t)((wm * 64 + (lid & 15)) * ROWB + (lid >> 4) * 16);
    const int bmi = lid >> 3, bwi = lid & 7;
    const uint32_t b_lane = (uint32_t)((wn * 64 + ((bmi >> 1) << 3) + bwi) * ROWB
                                       + (bmi & 1) * 16);

    load_stage(Ah, Al, Wh, Wl, rowBase, colBase, 0, sbase, tid);
    CP_COMMIT();

    for (int ch = 0; ch < 32; ch++) {
        CP_WAIT_ALL();
        __syncthreads();
        if (ch + 1 < 32) {
            load_stage(Ah, Al, Wh, Wl, rowBase, colBase, (ch + 1) * 32,
                       sbase + ((ch + 1) & 1) * STAGE_TOTAL, tid);
            CP_COMMIT();
        }
        const uint32_t sA = sbase + (ch & 1) * STAGE_TOTAL;
        const uint32_t sB = sA + 2 * STAGE_A;

#pragma unroll
        for (int kk = 0; kk < 2; kk++) {
            const uint32_t kb = kk * 32;
            uint32_t af[4][4], bh[4][4], bl[4][4];
#pragma unroll
            for (int mt = 0; mt < 4; mt++)
                LDSM_X4(af[mt][0], af[mt][1], af[mt][2], af[mt][3],
                        sA + a_lane + mt * (16 * ROWB) + kb);
#pragma unroll
            for (int np = 0; np < 4; np++)
                LDSM_X4(bh[np][0], bh[np][1], bh[np][2], bh[np][3],
                        sB + b_lane + np * (16 * ROWB) + kb);
#pragma unroll
            for (int np = 0; np < 4; np++)
                LDSM_X4(bl[np][0], bl[np][1], bl[np][2], bl[np][3],
                        sB + STAGE_B + b_lane + np * (16 * ROWB) + kb);

#pragma unroll
            for (int mt = 0; mt < 4; mt++)
#pragma unroll
                for (int np = 0; np < 4; np++) {
                    MMA16816(c[mt][np * 2],     af[mt], bh[np][0], bh[np][1]);
                    MMA16816(c[mt][np * 2 + 1], af[mt], bh[np][2], bh[np][3]);
                    MMA16816(c[mt][np * 2],     af[mt], bl[np][0], bl[np][1]);
                    MMA16816(c[mt][np * 2 + 1], af[mt], bl[np][2], bl[np][3]);
                }
#pragma unroll
            for (int mt = 0; mt < 4; mt++)
                LDSM_X4(af[mt][0], af[mt][1], af[mt][2], af[mt][3],
                        sA + STAGE_A + a_lane + mt * (16 * ROWB) + kb);
#pragma unroll
            for (int mt = 0; mt < 4; mt++)
#pragma unroll
                for (int np = 0; np < 4; np++) {
                    MMA16816(c[mt][np * 2],     af[mt], bh[np][0], bh[np][1]);
                    MMA16816(c[mt][np * 2 + 1], af[mt], bh[np][2], bh[np][3]);
                }
        }
    }

    const int r0 = rowBase + wm * 64 + (lid >> 2);
    const int c0 = colBase + wn * 64 + (lid & 3) * 2;
#pragma unroll
    for (int mt = 0; mt < 4; mt++) {
#pragma unroll
        for (int nt = 0; nt < 8; nt++) {
            const int row = r0 + mt * 16;
            const int col = c0 + nt * 8;
            float2 bv = *(const float2*)&bias[col];
            float2 v0, v1;
            v0.x = c[mt][nt][0] + bv.x; v0.y = c[mt][nt][1] + bv.y;
            v1.x = c[mt][nt][2] + bv.x; v1.y = c[mt][nt][3] + bv.y;
            *(float2*)&C[(size_t)row * D_EMB + col] = v0;
            *(float2*)&C[(size_t)(row + 8) * D_EMB + col] = v1;
        }
    }
}

// ---------------------------------------------------------------------------
// Flash attention (fp32 SIMT) with FMA-pipe exp
// ---------------------------------------------------------------------------
#define SMEM_FLOATS (64*64*3 + 64*LDK)
#define ATTN_SMEM_BYTES  (SMEM_FLOATS * 4)

__global__ __launch_bounds__(256, 2)
void attn_kernel(const float* __restrict__ Q, const float* __restrict__ K,
                 const float* __restrict__ V, float* __restrict__ O)
{
    extern __shared__ float smf[];
    float* Qs = smf;
    float* Kt = Qs + 64 * 64;
    float* Vs = Kt + 64 * LDK;
    float* Ps = Vs + 64 * 64;

    const int tid = threadIdx.x;
    const int tx = tid & 15;
    const int ty = tid >> 4;
    const int qt = blockIdx.x;
    const int h  = blockIdx.y;
    const int b  = blockIdx.z;

    const size_t qRow0 = (size_t)b * S_LEN + (size_t)qt * 64;
    const int colH = h * DH;

#pragma unroll
    for (int u = 0; u < 4; u++) {
        int s = tid + u * 256;
        int r = s >> 4;
        int dq = (s & 15) << 2;
        float4 v = *(const float4*)&Q[(qRow0 + r) * D_EMB + colH + dq];
        *(float4*)&Qs[r * 64 + dq] = v;
    }

    float o[4][4];
    float mrow[4], lrow[4];
#pragma unroll
    for (int i = 0; i < 4; i++) {
        mrow[i] = -INFINITY;
        lrow[i] = 0.f;
#pragma unroll
        for (int j = 0; j < 4; j++) o[i][j] = 0.f;
    }

    const float scale = 0.03125f;

    for (int kt = 0; kt <= qt; kt++) {
        __syncthreads();
        const size_t kRow0 = (size_t)b * S_LEN + (size_t)kt * 64;
#pragma unroll
        for (int u = 0; u < 4; u++) {
            int s = tid + u * 256;
            int c2 = s >> 4;
            int dq = (s & 15) << 2;
            float4 kv = *(const float4*)&K[(kRow0 + c2) * D_EMB + colH + dq];
            Kt[(dq + 0) * LDK + c2] = kv.x;
            Kt[(dq + 1) * LDK + c2] = kv.y;
            Kt[(dq + 2) * LDK + c2] = kv.z;
            Kt[(dq + 3) * LDK + c2] = kv.w;
            float4 vv = *(const float4*)&V[(kRow0 + c2) * D_EMB + colH + dq];
            *(float4*)&Vs[c2 * 64 + dq] = vv;
        }
        __syncthreads();

        float s4[4][4];
#pragma unroll
        for (int i = 0; i < 4; i++)
#pragma unroll
            for (int j = 0; j < 4; j++) s4[i][j] = 0.f;

#pragma unroll 4
        for (int d = 0; d < 64; d += 4) {
            float4 q4[4], k4[4];
#pragma unroll
            for (int i = 0; i < 4; i++)
                q4[i] = *(const float4*)&Qs[(ty * 4 + i) * 64 + d];
#pragma unroll
            for (int e = 0; e < 4; e++)
                k4[e] = *(const float4*)&Kt[(d + e) * LDK + tx * 4];
#pragma unroll
            for (int i = 0; i < 4; i++) {
                float q0 = q4[i].x, q1 = q4[i].y, q2 = q4[i].z, q3 = q4[i].w;
#define SDOT(jj, comp)                                      \
                s4[i][jj] = fmaf(q0, k4[0].comp, s4[i][jj]); \
                s4[i][jj] = fmaf(q1, k4[1].comp, s4[i][jj]); \
                s4[i][jj] = fmaf(q2, k4[2].comp, s4[i][jj]); \
                s4[i][jj] = fmaf(q3, k4[3].comp, s4[i][jj]);
                SDOT(0, x) SDOT(1, y) SDOT(2, z) SDOT(3, w)
#undef SDOT
            }
        }

        if (kt == qt) {
#pragma unroll
            for (int i = 0; i < 4; i++)
#pragma unroll
                for (int j = 0; j < 4; j++) {
                    int rl = ty * 4 + i, cl = tx * 4 + j;
                    s4[i][j] = (cl > rl) ? -INFINITY : s4[i][j] * scale;
                }
        } else {
#pragma unroll
            for (int i = 0; i < 4; i++)
#pragma unroll
                for (int j = 0; j < 4; j++) s4[i][j] *= scale;
        }

#pragma unroll
        for (int i = 0; i < 4; i++) {
            float rmax = fmaxf(fmaxf(s4[i][0], s4[i][1]), fmaxf(s4[i][2], s4[i][3]));
            rmax = fmaxf(rmax, __shfl_xor_sync(0xffffffffu, rmax, 8));
            rmax = fmaxf(rmax, __shfl_xor_sync(0xffffffffu, rmax, 4));
            rmax = fmaxf(rmax, __shfl_xor_sync(0xffffffffu, rmax, 2));
            rmax = fmaxf(rmax, __shfl_xor_sync(0xffffffffu, rmax, 1));
            float mnew = fmaxf(mrow[i], rmax);
            float p0 = fast_exp(s4[i][0] - mnew);
            float p1 = fast_exp(s4[i][1] - mnew);
            float p2 = fast_exp(s4[i][2] - mnew);
            float p3 = fast_exp(s4[i][3] - mnew);
            float sum = (p0 + p1) + (p2 + p3);
            sum += __shfl_xor_sync(0xffffffffu, sum, 8);
            sum += __shfl_xor_sync(0xffffffffu, sum, 4);
            sum += __shfl_xor_sync(0xffffffffu, sum, 2);
            sum += __shfl_xor_sync(0xffffffffu, sum, 1);
            float alpha = fast_exp(mrow[i] - mnew);
            lrow[i] = lrow[i] * alpha + sum;
            mrow[i] = mnew;
            o[i][0] *= alpha; o[i][1] *= alpha; o[i][2] *= alpha; o[i][3] *= alpha;
            float4 pw = make_float4(p0, p1, p2, p3);
            *(float4*)&Ps[(ty * 4 + i) * 64 + tx * 4] = pw;
        }
        __syncthreads();

#pragma unroll 4
        for (int c2 = 0; c2 < 64; c2 += 4) {
            float4 p4[4], v4[4];
#pragma unroll
            for (int i = 0; i < 4; i++)
                p4[i] = *(const float4*)&Ps[(ty * 4 + i) * 64 + c2];
#pragma unroll
            for (int e = 0; e < 4; e++)
                v4[e] = *(const float4*)&Vs[(c2 + e) * 64 + tx * 4];
#pragma unroll
            for (int i = 0; i < 4; i++) {
                float p0 = p4[i].x, p1 = p4[i].y, p2 = p4[i].z, p3 = p4[i].w;
#define PVDOT(jj, comp)                                     \
                o[i][jj] = fmaf(p0, v4[0].comp, o[i][jj]);   \
                o[i][jj] = fmaf(p1, v4[1].comp, o[i][jj]);   \
                o[i][jj] = fmaf(p2, v4[2].comp, o[i][jj]);   \
                o[i][jj] = fmaf(p3, v4[3].comp, o[i][jj]);
                PVDOT(0, x) PVDOT(1, y) PVDOT(2, z) PVDOT(3, w)
#undef PVDOT
            }
        }
    }

#pragma unroll
    for (int i = 0; i < 4; i++) {
        float inv = 1.f / lrow[i];
        float4 r;
        r.x = o[i][0] * inv; r.y = o[i][1] * inv;
        r.z = o[i][2] * inv; r.w = o[i][3] * inv;
        *(float4*)&O[(qRow0 + ty * 4 + i) * D_EMB + colH + tx * 4] = r;
    }
}

// ---------------------------------------------------------------------------
extern "C" void kernel_launch(void* const* d_in, const int* in_sizes, int n_in,
                              void* d_out, int out_size)
{
    const float* x  = (const float*)d_in[0];
    const float* Wq = (const float*)d_in[1];
    const float* bq = (const float*)d_in[2];
    const float* Wk = (const float*)d_in[3];
    const float* bk = (const float*)d_in[4];
    const float* Wv = (const float*)d_in[5];
    const float* bv = (const float*)d_in[6];
    const float* Wo = (const float*)d_in[7];
    const float* bo = (const float*)d_in[8];
    float* out = (float*)d_out;

    float *gq, *gk, *gv, *ga;
    cudaGetSymbolAddress((void**)&gq, g_q);
    cudaGetSymbolAddress((void**)&gk, g_k);
    cudaGetSymbolAddress((void**)&gv, g_v);
    cudaGetSymbolAddress((void**)&ga, g_attn);
    __nv_bfloat16 *xh, *xl, *ah, *al;
    cudaGetSymbolAddress((void**)&xh, g_xh);
    cudaGetSymbolAddress((void**)&xl, g_xl);
    cudaGetSymbolAddress((void**)&ah, g_ah);
    cudaGetSymbolAddress((void**)&al, g_al);
    __nv_bfloat16 *wqh, *wql, *wkh, *wkl, *wvh, *wvl, *woh, *wol;
    cudaGetSymbolAddress((void**)&wqh, g_wqh);
    cudaGetSymbolAddress((void**)&wql, g_wql);
    cudaGetSymbolAddress((void**)&wkh, g_wkh);
    cudaGetSymbolAddress((void**)&wkl, g_wkl);
    cudaGetSymbolAddress((void**)&wvh, g_wvh);
    cudaGetSymbolAddress((void**)&wvl, g_wvl);
    cudaGetSymbolAddress((void**)&woh, g_woh);
    cudaGetSymbolAddress((void**)&wol, g_wol);

    cudaFuncSetAttribute(attn_kernel, cudaFuncAttributeMaxDynamicSharedMemorySize,
                         ATTN_SMEM_BYTES);
    cudaFuncSetAttribute(mma_gemm_bias_kernel,
                         cudaFuncAttributeMaxDynamicSharedMemorySize, GEMM_SMEM);

    const int n4 = MROWS * D_EMB / 4;
    dim3 tgrid(32, 32), tblk(32, 8);
    dim3 ggrid(D_EMB / 256, MROWS / 128);

    split_bf16_kernel<<<(n4 + 255) / 256, 256>>>(x, xh, xl, n4);
    transpose_split_kernel<<<tgrid, tblk>>>(Wq, wqh, wql);
    transpose_split_kernel<<<tgrid, tblk>>>(Wk, wkh, wkl);
    transpose_split_kernel<<<tgrid, tblk>>>(Wv, wvh, wvl);
    transpose_split_kernel<<<tgrid, tblk>>>(Wo, woh, wol);

    mma_gemm_bias_kernel<<<ggrid, 256, GEMM_SMEM>>>(xh, xl, wqh, wql, bq, gq);
    mma_gemm_bias_kernel<<<ggrid, 256, GEMM_SMEM>>>(xh, xl, wkh, wkl, bk, gk);
    mma_gemm_bias_kernel<<<ggrid, 256, GEMM_SMEM>>>(xh, xl, wvh, wvl, bv, gv);

    attn_kernel<<<dim3(S_LEN / 64, NHEAD, BATCH), 256, ATTN_SMEM_BYTES>>>(gq, gk, gv, ga);

    split_bf16_kernel<<<(n4 + 255) / 256, 256>>>(ga, ah, al, n4);
    mma_gemm_bias_kernel<<<ggrid, 256, GEMM_SMEM>>>(ah, al, woh, wol, bo, out);
}

// round 8
// speedup vs baseline: 1.7576x; 1.7576x over previous
#include <cuda_runtime.h>
#include <cuda_bf16.h>
#include <cuda_fp16.h>
#include <math.h>
#include <stdint.h>

#define S_LEN 2048
#define D_EMB 1024
#define NHEAD 16
#define DH    64
#define BATCH 2
#define MROWS (BATCH * S_LEN)   // 4096

// ---------------- device scratch ----------------
__device__ __nv_bfloat16 g_xh[MROWS * D_EMB];
__device__ __nv_bfloat16 g_xl[MROWS * D_EMB];
__device__ __nv_bfloat16 g_ah[MROWS * D_EMB];
__device__ __nv_bfloat16 g_al[MROWS * D_EMB];

__device__ __half g_qh[MROWS * D_EMB];
__device__ __half g_ql[MROWS * D_EMB];
__device__ __half g_kh[MROWS * D_EMB];
__device__ __half g_vh[MROWS * D_EMB];
__device__ __half g_vl[MROWS * D_EMB];

__device__ __nv_bfloat16 g_wqh[D_EMB * D_EMB];
__device__ __nv_bfloat16 g_wql[D_EMB * D_EMB];
__device__ __nv_bfloat16 g_wkh[D_EMB * D_EMB];
__device__ __nv_bfloat16 g_wkl[D_EMB * D_EMB];
__device__ __nv_bfloat16 g_wvh[D_EMB * D_EMB];
__device__ __nv_bfloat16 g_wvl[D_EMB * D_EMB];
__device__ __nv_bfloat16 g_woh[D_EMB * D_EMB];
__device__ __nv_bfloat16 g_wol[D_EMB * D_EMB];

// ---------------- helpers ----------------
__device__ __forceinline__ uint32_t smem_to_u32(const void* p) {
    uint32_t a;
    asm("{ .reg .u64 t; cvta.to.shared.u64 t, %1; cvt.u32.u64 %0, t; }"
        : "=r"(a) : "l"(p));
    return a;
}

__device__ __forceinline__ void cp16(uint32_t s, const void* g) {
    asm volatile("cp.async.cg.shared.global [%0], [%1], 16;" :: "r"(s), "l"(g));
}
#define CP_COMMIT()  asm volatile("cp.async.commit_group;" ::: "memory")
#define CP_WAIT_ALL() asm volatile("cp.async.wait_group 0;" ::: "memory")
#define CP_WAIT_1()  asm volatile("cp.async.wait_group 1;" ::: "memory")

#define LDSM_X4(r0, r1, r2, r3, addr) \
    asm volatile("ldmatrix.sync.aligned.m8n8.x4.shared.b16 {%0,%1,%2,%3}, [%4];" \
        : "=r"(r0), "=r"(r1), "=r"(r2), "=r"(r3) : "r"(addr))

#define LDSM_X4T(r0, r1, r2, r3, addr) \
    asm volatile("ldmatrix.sync.aligned.m8n8.x4.trans.shared.b16 {%0,%1,%2,%3}, [%4];" \
        : "=r"(r0), "=r"(r1), "=r"(r2), "=r"(r3) : "r"(addr))

#define MMA16816(c, a, b0, b1) \
    asm volatile("mma.sync.aligned.m16n8k16.row.col.f32.bf16.bf16.f32 " \
        "{%0,%1,%2,%3}, {%4,%5,%6,%7}, {%8,%9}, {%0,%1,%2,%3};" \
        : "+f"((c)[0]), "+f"((c)[1]), "+f"((c)[2]), "+f"((c)[3]) \
        : "r"((a)[0]), "r"((a)[1]), "r"((a)[2]), "r"((a)[3]), "r"(b0), "r"(b1))

#define MMAH(c, a0, a1, a2, a3, b0, b1) \
    asm volatile("mma.sync.aligned.m16n8k16.row.col.f32.f16.f16.f32 " \
        "{%0,%1,%2,%3}, {%4,%5,%6,%7}, {%8,%9}, {%0,%1,%2,%3};" \
        : "+f"((c)[0]), "+f"((c)[1]), "+f"((c)[2]), "+f"((c)[3]) \
        : "r"(a0), "r"(a1), "r"(a2), "r"(a3), "r"(b0), "r"(b1))

// FMA-pipe exp: exp(x) = 2^(x*log2e), deg-5 on [-0.5,0.5]; valid x <= 0.
__device__ __forceinline__ float fast_exp(float x) {
    x = fmaxf(x, -87.0f);
    float y = fmaf(x, 1.4426950408889634f, 12582912.0f);
    int   e = __float_as_int(y) - 0x4B400000;
    float i = y - 12582912.0f;
    float f = fmaf(x, 1.4426950408889634f, -i);
    float p =           1.3333558e-3f;
    p = fmaf(p, f, 9.6181291e-3f);
    p = fmaf(p, f, 5.5504109e-2f);
    p = fmaf(p, f, 2.4022651e-1f);
    p = fmaf(p, f, 6.9314718e-1f);
    p = fmaf(p, f, 1.0f);
    return p * __int_as_float((127 + e) << 23);
}

// ---------------------------------------------------------------------------
// split fp32 -> bf16 hi/lo
// ---------------------------------------------------------------------------
__global__ __launch_bounds__(256)
void split_bf16_kernel(const float* __restrict__ in,
                       __nv_bfloat16* __restrict__ hi,
                       __nv_bfloat16* __restrict__ lo, int n4)
{
    int idx = blockIdx.x * 256 + threadIdx.x;
    if (idx >= n4) return;
    float4 v = *(const float4*)(in + (size_t)idx * 4);
    __nv_bfloat16 h0 = __float2bfloat16(v.x);
    __nv_bfloat16 h1 = __float2bfloat16(v.y);
    __nv_bfloat16 h2 = __float2bfloat16(v.z);
    __nv_bfloat16 h3 = __float2bfloat16(v.w);
    __nv_bfloat16 l0 = __float2bfloat16(v.x - __bfloat162float(h0));
    __nv_bfloat16 l1 = __float2bfloat16(v.y - __bfloat162float(h1));
    __nv_bfloat16 l2 = __float2bfloat16(v.z - __bfloat162float(h2));
    __nv_bfloat16 l3 = __float2bfloat16(v.w - __bfloat162float(h3));
    __nv_bfloat162* hp = (__nv_bfloat162*)(hi + (size_t)idx * 4);
    __nv_bfloat162* lp = (__nv_bfloat162*)(lo + (size_t)idx * 4);
    hp[0] = __nv_bfloat162(h0, h1);
    hp[1] = __nv_bfloat162(h2, h3);
    lp[0] = __nv_bfloat162(l0, l1);
    lp[1] = __nv_bfloat162(l2, l3);
}

// ---------------------------------------------------------------------------
// transpose + split:  Wt[n,k] = W[k,n]  (1024x1024)
// ---------------------------------------------------------------------------
__global__ __launch_bounds__(256)
void transpose_split_kernel(const float* __restrict__ W,
                            __nv_bfloat16* __restrict__ th,
                            __nv_bfloat16* __restrict__ tl)
{
    __shared__ float t[32][33];
    const int tx = threadIdx.x, ty = threadIdx.y;  // 32 x 8
    const int n0 = blockIdx.x * 32;
    const int k0 = blockIdx.y * 32;
#pragma unroll
    for (int i = 0; i < 4; i++)
        t[ty + i * 8][tx] = W[(size_t)(k0 + ty + i * 8) * D_EMB + n0 + tx];
    __syncthreads();
#pragma unroll
    for (int i = 0; i < 4; i++) {
        int n = n0 + ty + i * 8;
        int k = k0 + tx;
        float v = t[tx][ty + i * 8];
        __nv_bfloat16 h = __float2bfloat16(v);
        __nv_bfloat16 l = __float2bfloat16(v - __bfloat162float(h));
        th[(size_t)n * D_EMB + k] = h;
        tl[(size_t)n * D_EMB + k] = l;
    }
}

// ---------------------------------------------------------------------------
// mma.sync GEMM: C = (Ah+Al) @ (Wh+Wl)^T + bias, with optional fp32/fp16 out
// ---------------------------------------------------------------------------
#define ROWB      80
#define STAGE_A   (128 * ROWB)
#define STAGE_B   (256 * ROWB)
#define STAGE_TOTAL (2 * STAGE_A + 2 * STAGE_B)
#define GEMM_SMEM (2 * STAGE_TOTAL)

__device__ __forceinline__ void load_stage(
    const __nv_bfloat16* __restrict__ Ah, const __nv_bfloat16* __restrict__ Al,
    const __nv_bfloat16* __restrict__ Bh, const __nv_bfloat16* __restrict__ Bl,
    int rowBase, int colBase, int k0, uint32_t sbase, int tid)
{
#pragma unroll
    for (int i = 0; i < 2; i++) {
        int c = tid * 2 + i;
        int r = c >> 2, kc = c & 3;
        size_t goff = (size_t)(rowBase + r) * D_EMB + k0 + kc * 8;
        uint32_t soff = r * ROWB + kc * 16;
        cp16(sbase + soff, Ah + goff);
        cp16(sbase + STAGE_A + soff, Al + goff);
    }
#pragma unroll
    for (int i = 0; i < 4; i++) {
        int c = tid * 4 + i;
        int r = c >> 2, kc = c & 3;
        size_t goff = (size_t)(colBase + r) * D_EMB + k0 + kc * 8;
        uint32_t soff = r * ROWB + kc * 16;
        cp16(sbase + 2 * STAGE_A + soff, Bh + goff);
        cp16(sbase + 2 * STAGE_A + STAGE_B + soff, Bl + goff);
    }
}

__global__ __launch_bounds__(256, 1)
void mma_gemm_bias_kernel(const __nv_bfloat16* __restrict__ Ah,
                          const __nv_bfloat16* __restrict__ Al,
                          const __nv_bfloat16* __restrict__ Wh,
                          const __nv_bfloat16* __restrict__ Wl,
                          const float* __restrict__ bias,
                          float* __restrict__ C,
                          __half* __restrict__ H,
                          __half* __restrict__ L)
{
    extern __shared__ char smem[];
    const uint32_t sbase = smem_to_u32(smem);
    const int tid = threadIdx.x;
    const int wid = tid >> 5;
    const int lid = tid & 31;
    const int wm = wid & 1;
    const int wn = wid >> 1;
    const int rowBase = blockIdx.y * 128;
    const int colBase = blockIdx.x * 256;

    float c[4][8][4];
#pragma unroll
    for (int i = 0; i < 4; i++)
#pragma unroll
        for (int j = 0; j < 8; j++)
#pragma unroll
            for (int q = 0; q < 4; q++) c[i][j][q] = 0.f;

    const uint32_t a_lane = (uint32_t)((wm * 64 + (lid & 15)) * ROWB + (lid >> 4) * 16);
    const int bmi = lid >> 3, bwi = lid & 7;
    const uint32_t b_lane = (uint32_t)((wn * 64 + ((bmi >> 1) << 3) + bwi) * ROWB
                                       + (bmi & 1) * 16);

    load_stage(Ah, Al, Wh, Wl, rowBase, colBase, 0, sbase, tid);
    CP_COMMIT();

    for (int ch = 0; ch < 32; ch++) {
        CP_WAIT_ALL();
        __syncthreads();
        if (ch + 1 < 32) {
            load_stage(Ah, Al, Wh, Wl, rowBase, colBase, (ch + 1) * 32,
                       sbase + ((ch + 1) & 1) * STAGE_TOTAL, tid);
            CP_COMMIT();
        }
        const uint32_t sA = sbase + (ch & 1) * STAGE_TOTAL;
        const uint32_t sB = sA + 2 * STAGE_A;

#pragma unroll
        for (int kk = 0; kk < 2; kk++) {
            const uint32_t kb = kk * 32;
            uint32_t af[4][4], bh[4][4], bl[4][4];
#pragma unroll
            for (int mt = 0; mt < 4; mt++)
                LDSM_X4(af[mt][0], af[mt][1], af[mt][2], af[mt][3],
                        sA + a_lane + mt * (16 * ROWB) + kb);
#pragma unroll
            for (int np = 0; np < 4; np++)
                LDSM_X4(bh[np][0], bh[np][1], bh[np][2], bh[np][3],
                        sB + b_lane + np * (16 * ROWB) + kb);
#pragma unroll
            for (int np = 0; np < 4; np++)
                LDSM_X4(bl[np][0], bl[np][1], bl[np][2], bl[np][3],
                        sB + STAGE_B + b_lane + np * (16 * ROWB) + kb);

#pragma unroll
            for (int mt = 0; mt < 4; mt++)
#pragma unroll
                for (int np = 0; np < 4; np++) {
                    MMA16816(c[mt][np * 2],     af[mt], bh[np][0], bh[np][1]);
                    MMA16816(c[mt][np * 2 + 1], af[mt], bh[np][2], bh[np][3]);
                    MMA16816(c[mt][np * 2],     af[mt], bl[np][0], bl[np][1]);
                    MMA16816(c[mt][np * 2 + 1], af[mt], bl[np][2], bl[np][3]);
                }
#pragma unroll
            for (int mt = 0; mt < 4; mt++)
                LDSM_X4(af[mt][0], af[mt][1], af[mt][2], af[mt][3],
                        sA + STAGE_A + a_lane + mt * (16 * ROWB) + kb);
#pragma unroll
            for (int mt = 0; mt < 4; mt++)
#pragma unroll
                for (int np = 0; np < 4; np++) {
                    MMA16816(c[mt][np * 2],     af[mt], bh[np][0], bh[np][1]);
                    MMA16816(c[mt][np * 2 + 1], af[mt], bh[np][2], bh[np][3]);
                }
        }
    }

    const int r0 = rowBase + wm * 64 + (lid >> 2);
    const int c0 = colBase + wn * 64 + (lid & 3) * 2;
#pragma unroll
    for (int mt = 0; mt < 4; mt++) {
#pragma unroll
        for (int nt = 0; nt < 8; nt++) {
            const int row = r0 + mt * 16;
            const int col = c0 + nt * 8;
            float2 bv = *(const float2*)&bias[col];
            float v00 = c[mt][nt][0] + bv.x, v01 = c[mt][nt][1] + bv.y;
            float v10 = c[mt][nt][2] + bv.x, v11 = c[mt][nt][3] + bv.y;
            if (C) {
                *(float2*)&C[(size_t)row * D_EMB + col] = make_float2(v00, v01);
                *(float2*)&C[(size_t)(row + 8) * D_EMB + col] = make_float2(v10, v11);
            }
            if (H) {
                __half h00 = __float2half_rn(v00), h01 = __float2half_rn(v01);
                __half h10 = __float2half_rn(v10), h11 = __float2half_rn(v11);
                *(__half2*)&H[(size_t)row * D_EMB + col] = __half2(h00, h01);
                *(__half2*)&H[(size_t)(row + 8) * D_EMB + col] = __half2(h10, h11);
                if (L) {
                    __half e00 = __float2half_rn(v00 - __half2float(h00));
                    __half e01 = __float2half_rn(v01 - __half2float(h01));
                    __half e10 = __float2half_rn(v10 - __half2float(h10));
                    __half e11 = __float2half_rn(v11 - __half2float(h11));
                    *(__half2*)&L[(size_t)row * D_EMB + col] = __half2(e00, e01);
                    *(__half2*)&L[(size_t)(row + 8) * D_EMB + col] = __half2(e10, e11);
                }
            }
        }
    }
}

// ---------------------------------------------------------------------------
// Tensor-core flash attention.
//   CTA = 128 q-rows x 1 head. 8 warps x 16 rows. KV blocks of 64, 2-stage.
//   Scores: (Qh + Ql) @ Kh^T ; P fp16 (l from rounded p) ; out: P@(Vh+Vl).
//   Smem rows padded to 144 B for conflict-free ldmatrix.
// ---------------------------------------------------------------------------
#define AROW     144
#define SM_QH    0
#define SM_QL    18432
#define SM_KV    36864
#define KV_STAGE 27648
#define KT_OFF   0
#define VH_OFF   9216
#define VL_OFF   18432
#define ATT_SMEM (SM_KV + 2 * KV_STAGE)   // 92160

__global__ __launch_bounds__(256, 2)
void attn_mma_kernel(const __half* __restrict__ Qh, const __half* __restrict__ Ql,
                     const __half* __restrict__ Kh, const __half* __restrict__ Vh,
                     const __half* __restrict__ Vl,
                     __nv_bfloat16* __restrict__ Oh, __nv_bfloat16* __restrict__ Ol)
{
    extern __shared__ char sm[];
    const uint32_t sb = smem_to_u32(sm);
    const int tid = threadIdx.x, wid = tid >> 5, lid = tid & 31;
    const int qt = 15 - (int)blockIdx.x;        // longest CTAs first
    const int h = blockIdx.y, b = blockIdx.z;
    const size_t qRow0 = (size_t)b * S_LEN + (size_t)qt * 128;
    const int colH = h * DH;
    const int kbmax = 2 * qt + 1;

    // preload Q (hi/lo) + KV block 0 as one cp.async group
#pragma unroll
    for (int t = 0; t < 8; t++) {
        int idx = tid + t * 256;
        int tile = idx >> 10;                   // 0=Qh 1=Ql
        int r = (idx >> 3) & 127, cc = idx & 7;
        const __half* src = (tile ? Ql : Qh) + (qRow0 + r) * D_EMB + colH + cc * 8;
        cp16(sb + (tile ? SM_QL : SM_QH) + r * AROW + cc * 16, src);
    }
    {
        size_t kRow0 = (size_t)b * S_LEN;
#pragma unroll
        for (int t = 0; t < 6; t++) {
            int idx = tid + t * 256;
            int tile = idx >> 9;                // 0=K 1=Vh 2=Vl
            int r = (idx >> 3) & 63, cc = idx & 7;
            const __half* src = (tile == 0 ? Kh : (tile == 1 ? Vh : Vl))
                                + (kRow0 + r) * D_EMB + colH + cc * 8;
            cp16(sb + SM_KV + tile * 9216 + r * AROW + cc * 16, src);
        }
    }
    CP_COMMIT();

    float m0 = -1e30f, m1 = -1e30f, l0 = 0.f, l1 = 0.f;
    float o[8][4];
#pragma unroll
    for (int j = 0; j < 8; j++)
#pragma unroll
        for (int q = 0; q < 4; q++) o[j][q] = 0.f;

    const uint32_t a_off = (uint32_t)((wid * 16 + (lid & 15)) * AROW + (lid >> 4) * 16);
    const int bmi = lid >> 3;
    const uint32_t k_off = (uint32_t)((((bmi >> 1) << 3) + (lid & 7)) * AROW + (bmi & 1) * 16);
    const uint32_t v_off = (uint32_t)((((bmi & 1) << 3) + (lid & 7)) * AROW + (lid >> 4) * 16);

    for (int kb = 0; kb <= kbmax; kb++) {
        __syncthreads();                        // everyone done with old buffer
        if (kb < kbmax) {
            size_t kRow0 = (size_t)b * S_LEN + (size_t)(kb + 1) * 64;
            uint32_t base = sb + SM_KV + ((kb + 1) & 1) * KV_STAGE;
#pragma unroll
            for (int t = 0; t < 6; t++) {
                int idx = tid + t * 256;
                int tile = idx >> 9;
                int r = (idx >> 3) & 63, cc = idx & 7;
                const __half* src = (tile == 0 ? Kh : (tile == 1 ? Vh : Vl))
                                    + (kRow0 + r) * D_EMB + colH + cc * 8;
                cp16(base + tile * 9216 + r * AROW + cc * 16, src);
            }
            CP_COMMIT();
            CP_WAIT_1();
        } else {
            CP_WAIT_ALL();
        }
        __syncthreads();                        // kb's data visible to all

        const uint32_t skv = sb + SM_KV + (kb & 1) * KV_STAGE;

        // ---- scores: c[8][4] = (Qh+Ql) @ Kh^T ----
        float c[8][4];
#pragma unroll
        for (int j = 0; j < 8; j++)
#pragma unroll
            for (int q = 0; q < 4; q++) c[j][q] = 0.f;

#pragma unroll
        for (int ks = 0; ks < 4; ks++) {
            uint32_t ah0, ah1, ah2, ah3, al0, al1, al2, al3;
            LDSM_X4(ah0, ah1, ah2, ah3, sb + SM_QH + a_off + ks * 32);
            LDSM_X4(al0, al1, al2, al3, sb + SM_QL + a_off + ks * 32);
#pragma unroll
            for (int np = 0; np < 4; np++) {
                uint32_t b0, b1, b2, b3;
                LDSM_X4(b0, b1, b2, b3, skv + KT_OFF + k_off + np * (16 * AROW) + ks * 32);
                MMAH(c[2 * np],     ah0, ah1, ah2, ah3, b0, b1);
                MMAH(c[2 * np + 1], ah0, ah1, ah2, ah3, b2, b3);
                MMAH(c[2 * np],     al0, al1, al2, al3, b0, b1);
                MMAH(c[2 * np + 1], al0, al1, al2, al3, b2, b3);
            }
        }

        // ---- scale + causal mask ----
        const int rA = qt * 128 + wid * 16 + (lid >> 2);
        const bool needMask = (kb * 64 + 63) > (qt * 128 + wid * 16);
#pragma unroll
        for (int j = 0; j < 8; j++) {
            int colg = kb * 64 + j * 8 + (lid & 3) * 2;
#pragma unroll
            for (int q = 0; q < 4; q++) {
                float s = c[j][q] * 0.03125f;
                if (needMask) {
                    int cg = colg + (q & 1);
                    int rr = rA + ((q >= 2) ? 8 : 0);
                    if (cg > rr) s = -1e30f;
                }
                c[j][q] = s;
            }
        }

        // ---- online softmax (rows rA and rA+8 per lane) ----
        float mxA = -1e30f, mxB = -1e30f;
#pragma unroll
        for (int j = 0; j < 8; j++) {
            mxA = fmaxf(mxA, fmaxf(c[j][0], c[j][1]));
            mxB = fmaxf(mxB, fmaxf(c[j][2], c[j][3]));
        }
        mxA = fmaxf(mxA, __shfl_xor_sync(0xffffffffu, mxA, 1));
        mxA = fmaxf(mxA, __shfl_xor_sync(0xffffffffu, mxA, 2));
        mxB = fmaxf(mxB, __shfl_xor_sync(0xffffffffu, mxB, 1));
        mxB = fmaxf(mxB, __shfl_xor_sync(0xffffffffu, mxB, 2));
        float mnA = fmaxf(m0, mxA), mnB = fmaxf(m1, mxB);
        float alA = fast_exp(m0 - mnA), alB = fast_exp(m1 - mnB);
        m0 = mnA; m1 = mnB;

        uint32_t pA[8], pB[8];
        float sA = 0.f, sB = 0.f;
#pragma unroll
        for (int j = 0; j < 8; j++) {
            __half2 hA = __floats2half2_rn(fast_exp(c[j][0] - mnA),
                                           fast_exp(c[j][1] - mnA));
            __half2 hB = __floats2half2_rn(fast_exp(c[j][2] - mnB),
                                           fast_exp(c[j][3] - mnB));
            pA[j] = *reinterpret_cast<uint32_t*>(&hA);
            pB[j] = *reinterpret_cast<uint32_t*>(&hB);
            sA += __low2float(hA) + __high2float(hA);   // l consistent with fp16 P
            sB += __low2float(hB) + __high2float(hB);
        }
        sA += __shfl_xor_sync(0xffffffffu, sA, 1);
        sA += __shfl_xor_sync(0xffffffffu, sA, 2);
        sB += __shfl_xor_sync(0xffffffffu, sB, 1);
        sB += __shfl_xor_sync(0xffffffffu, sB, 2);
        l0 = l0 * alA + sA;
        l1 = l1 * alB + sB;
#pragma unroll
        for (int j = 0; j < 8; j++) {
            o[j][0] *= alA; o[j][1] *= alA;
            o[j][2] *= alB; o[j][3] *= alB;
        }

        // ---- O += P @ (Vh + Vl) ----
#pragma unroll
        for (int ks = 0; ks < 4; ks++) {
            uint32_t a0 = pA[2 * ks], a1 = pB[2 * ks];
            uint32_t a2 = pA[2 * ks + 1], a3 = pB[2 * ks + 1];
#pragma unroll
            for (int np = 0; np < 4; np++) {
                uint32_t b0, b1, b2, b3;
                LDSM_X4T(b0, b1, b2, b3,
                         skv + VH_OFF + v_off + ks * (16 * AROW) + np * 32);
                MMAH(o[2 * np],     a0, a1, a2, a3, b0, b1);
                MMAH(o[2 * np + 1], a0, a1, a2, a3, b2, b3);
                LDSM_X4T(b0, b1, b2, b3,
                         skv + VL_OFF + v_off + ks * (16 * AROW) + np * 32);
                MMAH(o[2 * np],     a0, a1, a2, a3, b0, b1);
                MMAH(o[2 * np + 1], a0, a1, a2, a3, b2, b3);
            }
        }
    }

    // ---- normalize + write bf16 hi/lo (feeds Wo GEMM) ----
    const float invA = 1.f / l0, invB = 1.f / l1;
    const size_t rowA = qRow0 + wid * 16 + (lid >> 2);
#pragma unroll
    for (int j = 0; j < 8; j++) {
        int col = colH + j * 8 + (lid & 3) * 2;
        float v0 = o[j][0] * invA, v1 = o[j][1] * invA;
        float v2 = o[j][2] * invB, v3 = o[j][3] * invB;
        __nv_bfloat16 h0 = __float2bfloat16(v0), h1 = __float2bfloat16(v1);
        __nv_bfloat16 h2 = __float2bfloat16(v2), h3 = __float2bfloat16(v3);
        __nv_bfloat16 e0 = __float2bfloat16(v0 - __bfloat162float(h0));
        __nv_bfloat16 e1 = __float2bfloat16(v1 - __bfloat162float(h1));
        __nv_bfloat16 e2 = __float2bfloat16(v2 - __bfloat162float(h2));
        __nv_bfloat16 e3 = __float2bfloat16(v3 - __bfloat162float(h3));
        *(__nv_bfloat162*)&Oh[rowA * D_EMB + col] = __nv_bfloat162(h0, h1);
        *(__nv_bfloat162*)&Ol[rowA * D_EMB + col] = __nv_bfloat162(e0, e1);
        *(__nv_bfloat162*)&Oh[(rowA + 8) * D_EMB + col] = __nv_bfloat162(h2, h3);
        *(__nv_bfloat162*)&Ol[(rowA + 8) * D_EMB + col] = __nv_bfloat162(e2, e3);
    }
}

// ---------------------------------------------------------------------------
extern "C" void kernel_launch(void* const* d_in, const int* in_sizes, int n_in,
                              void* d_out, int out_size)
{
    const float* x  = (const float*)d_in[0];
    const float* Wq = (const float*)d_in[1];
    const float* bq = (const float*)d_in[2];
    const float* Wk = (const float*)d_in[3];
    const float* bk = (const float*)d_in[4];
    const float* Wv = (const float*)d_in[5];
    const float* bv = (const float*)d_in[6];
    const float* Wo = (const float*)d_in[7];
    const float* bo = (const float*)d_in[8];
    float* out = (float*)d_out;

    __nv_bfloat16 *xh, *xl, *ah, *al;
    cudaGetSymbolAddress((void**)&xh, g_xh);
    cudaGetSymbolAddress((void**)&xl, g_xl);
    cudaGetSymbolAddress((void**)&ah, g_ah);
    cudaGetSymbolAddress((void**)&al, g_al);
    __half *qh, *ql, *kh, *vh, *vl;
    cudaGetSymbolAddress((void**)&qh, g_qh);
    cudaGetSymbolAddress((void**)&ql, g_ql);
    cudaGetSymbolAddress((void**)&kh, g_kh);
    cudaGetSymbolAddress((void**)&vh, g_vh);
    cudaGetSymbolAddress((void**)&vl, g_vl);
    __nv_bfloat16 *wqh, *wql, *wkh, *wkl, *wvh, *wvl, *woh, *wol;
    cudaGetSymbolAddress((void**)&wqh, g_wqh);
    cudaGetSymbolAddress((void**)&wql, g_wql);
    cudaGetSymbolAddress((void**)&wkh, g_wkh);
    cudaGetSymbolAddress((void**)&wkl, g_wkl);
    cudaGetSymbolAddress((void**)&wvh, g_wvh);
    cudaGetSymbolAddress((void**)&wvl, g_wvl);
    cudaGetSymbolAddress((void**)&woh, g_woh);
    cudaGetSymbolAddress((void**)&wol, g_wol);

    cudaFuncSetAttribute(mma_gemm_bias_kernel,
                         cudaFuncAttributeMaxDynamicSharedMemorySize, GEMM_SMEM);
    cudaFuncSetAttribute(attn_mma_kernel,
                         cudaFuncAttributeMaxDynamicSharedMemorySize, ATT_SMEM);

    const int n4 = MROWS * D_EMB / 4;
    dim3 tgrid(32, 32), tblk(32, 8);
    dim3 ggrid(D_EMB / 256, MROWS / 128);

    split_bf16_kernel<<<(n4 + 255) / 256, 256>>>(x, xh, xl, n4);
    transpose_split_kernel<<<tgrid, tblk>>>(Wq, wqh, wql);
    transpose_split_kernel<<<tgrid, tblk>>>(Wk, wkh, wkl);
    transpose_split_kernel<<<tgrid, tblk>>>(Wv, wvh, wvl);
    transpose_split_kernel<<<tgrid, tblk>>>(Wo, woh, wol);

    // projections: epilogue emits fp16 (hi/lo) directly for attention
    mma_gemm_bias_kernel<<<ggrid, 256, GEMM_SMEM>>>(xh, xl, wqh, wql, bq,
                                                    nullptr, qh, ql);
    mma_gemm_bias_kernel<<<ggrid, 256, GEMM_SMEM>>>(xh, xl, wkh, wkl, bk,
                                                    nullptr, kh, nullptr);
    mma_gemm_bias_kernel<<<ggrid, 256, GEMM_SMEM>>>(xh, xl, wvh, wvl, bv,
                                                    nullptr, vh, vl);

    attn_mma_kernel<<<dim3(S_LEN / 128, NHEAD, BATCH), 256, ATT_SMEM>>>(
        qh, ql, kh, vh, vl, ah, al);

    mma_gemm_bias_kernel<<<ggrid, 256, GEMM_SMEM>>>(ah, al, woh, wol, bo,
                                                    out, nullptr, nullptr);
}

// round 10
// speedup vs baseline: 2.6911x; 1.5311x over previous
#include <cuda_runtime.h>
#include <cuda_fp16.h>
#include <math.h>
#include <stdint.h>

#define S_LEN 2048
#define D_EMB 1024
#define NHEAD 16
#define DH    64
#define BATCH 2
#define MROWS (BATCH * S_LEN)   // 4096

// ---------------- device scratch ----------------
__device__ __half g_xh[MROWS * D_EMB];
__device__ __half g_xl[MROWS * D_EMB];
__device__ __half g_qh[MROWS * D_EMB];
__device__ __half g_kh[MROWS * D_EMB];
__device__ __half g_vh[MROWS * D_EMB];
__device__ __half g_ah[MROWS * D_EMB];
__device__ __half g_al[MROWS * D_EMB];

__device__ __half g_wq[D_EMB * D_EMB];
__device__ __half g_wk[D_EMB * D_EMB];
__device__ __half g_wv[D_EMB * D_EMB];
__device__ __half g_wo[D_EMB * D_EMB];

// ---------------- helpers ----------------
__device__ __forceinline__ uint32_t smem_to_u32(const void* p) {
    uint32_t a;
    asm("{ .reg .u64 t; cvta.to.shared.u64 t, %1; cvt.u32.u64 %0, t; }"
        : "=r"(a) : "l"(p));
    return a;
}

__device__ __forceinline__ void cp16(uint32_t s, const void* g) {
    asm volatile("cp.async.cg.shared.global [%0], [%1], 16;" :: "r"(s), "l"(g));
}
#define CP_COMMIT()  asm volatile("cp.async.commit_group;" ::: "memory")
#define CP_WAIT_ALL() asm volatile("cp.async.wait_group 0;" ::: "memory")
#define CP_WAIT_1()  asm volatile("cp.async.wait_group 1;" ::: "memory")

#define LDSM_X4(r0, r1, r2, r3, addr) \
    asm volatile("ldmatrix.sync.aligned.m8n8.x4.shared.b16 {%0,%1,%2,%3}, [%4];" \
        : "=r"(r0), "=r"(r1), "=r"(r2), "=r"(r3) : "r"(addr))

#define LDSM_X4T(r0, r1, r2, r3, addr) \
    asm volatile("ldmatrix.sync.aligned.m8n8.x4.trans.shared.b16 {%0,%1,%2,%3}, [%4];" \
        : "=r"(r0), "=r"(r1), "=r"(r2), "=r"(r3) : "r"(addr))

// fp16 mma, array A operand
#define MMAHX(c, a, b0, b1) \
    asm volatile("mma.sync.aligned.m16n8k16.row.col.f32.f16.f16.f32 " \
        "{%0,%1,%2,%3}, {%4,%5,%6,%7}, {%8,%9}, {%0,%1,%2,%3};" \
        : "+f"((c)[0]), "+f"((c)[1]), "+f"((c)[2]), "+f"((c)[3]) \
        : "r"((a)[0]), "r"((a)[1]), "r"((a)[2]), "r"((a)[3]), "r"(b0), "r"(b1))

// fp16 mma, scalar A operands
#define MMAH(c, a0, a1, a2, a3, b0, b1) \
    asm volatile("mma.sync.aligned.m16n8k16.row.col.f32.f16.f16.f32 " \
        "{%0,%1,%2,%3}, {%4,%5,%6,%7}, {%8,%9}, {%0,%1,%2,%3};" \
        : "+f"((c)[0]), "+f"((c)[1]), "+f"((c)[2]), "+f"((c)[3]) \
        : "r"(a0), "r"(a1), "r"(a2), "r"(a3), "r"(b0), "r"(b1))

// FMA-pipe exp: exp(x) = 2^(x*log2e), deg-5 on [-0.5,0.5]; valid x <= 0.
__device__ __forceinline__ float fast_exp(float x) {
    x = fmaxf(x, -87.0f);
    float y = fmaf(x, 1.4426950408889634f, 12582912.0f);
    int   e = __float_as_int(y) - 0x4B400000;
    float i = y - 12582912.0f;
    float f = fmaf(x, 1.4426950408889634f, -i);
    float p =           1.3333558e-3f;
    p = fmaf(p, f, 9.6181291e-3f);
    p = fmaf(p, f, 5.5504109e-2f);
    p = fmaf(p, f, 2.4022651e-1f);
    p = fmaf(p, f, 6.9314718e-1f);
    p = fmaf(p, f, 1.0f);
    return p * __int_as_float((127 + e) << 23);
}

// ---------------------------------------------------------------------------
// split fp32 -> fp16 hi/lo
// ---------------------------------------------------------------------------
__global__ __launch_bounds__(256)
void split_fp16_kernel(const float* __restrict__ in,
                       __half* __restrict__ hi, __half* __restrict__ lo, int n4)
{
    int idx = blockIdx.x * 256 + threadIdx.x;
    if (idx >= n4) return;
    float4 v = *(const float4*)(in + (size_t)idx * 4);
    __half h0 = __float2half_rn(v.x), h1 = __float2half_rn(v.y);
    __half h2 = __float2half_rn(v.z), h3 = __float2half_rn(v.w);
    __half l0 = __float2half_rn(v.x - __half2float(h0));
    __half l1 = __float2half_rn(v.y - __half2float(h1));
    __half l2 = __float2half_rn(v.z - __half2float(h2));
    __half l3 = __float2half_rn(v.w - __half2float(h3));
    __half2* hp = (__half2*)(hi + (size_t)idx * 4);
    __half2* lp = (__half2*)(lo + (size_t)idx * 4);
    hp[0] = __half2(h0, h1); hp[1] = __half2(h2, h3);
    lp[0] = __half2(l0, l1); lp[1] = __half2(l2, l3);
}

// ---------------------------------------------------------------------------
// transpose to fp16:  T[n,k] = (half)W[k,n]  (1024x1024)
// ---------------------------------------------------------------------------
__global__ __launch_bounds__(256)
void transpose_half_kernel(const float* __restrict__ W, __half* __restrict__ T)
{
    __shared__ float t[32][33];
    const int tx = threadIdx.x, ty = threadIdx.y;  // 32 x 8
    const int n0 = blockIdx.x * 32;
    const int k0 = blockIdx.y * 32;
#pragma unroll
    for (int i = 0; i < 4; i++)
        t[ty + i * 8][tx] = W[(size_t)(k0 + ty + i * 8) * D_EMB + n0 + tx];
    __syncthreads();
#pragma unroll
    for (int i = 0; i < 4; i++) {
        int n = n0 + ty + i * 8;
        int k = k0 + tx;
        T[(size_t)n * D_EMB + k] = __float2half_rn(t[tx][ty + i * 8]);
    }
}

// ---------------------------------------------------------------------------
// fp16 2-term GEMM: C = (Ah+Al) @ W^T + bias  (A hi/lo fp16, W single fp16)
//   CTA 128x256, 8 warps (2x4), warp tile 64x64, BK=32, 2-stage cp.async.
// ---------------------------------------------------------------------------
#define ROWB      80
#define STAGE_A   (128 * ROWB)             // 10240
#define STAGE_B   (256 * ROWB)             // 20480
#define STAGE_TOTAL (2 * STAGE_A + STAGE_B)  // 40960
#define GEMM_SMEM (2 * STAGE_TOTAL)        // 81920

__device__ __forceinline__ void load_stage(
    const __half* __restrict__ Ah, const __half* __restrict__ Al,
    const __half* __restrict__ Wh,
    int rowBase, int colBase, int k0, uint32_t sbase, int tid)
{
#pragma unroll
    for (int i = 0; i < 2; i++) {
        int c = tid * 2 + i;
        int r = c >> 2, kc = c & 3;
        size_t goff = (size_t)(rowBase + r) * D_EMB + k0 + kc * 8;
        uint32_t soff = r * ROWB + kc * 16;
        cp16(sbase + soff, Ah + goff);
        cp16(sbase + STAGE_A + soff, Al + goff);
    }
#pragma unroll
    for (int i = 0; i < 4; i++) {
        int c = tid * 4 + i;
        int r = c >> 2, kc = c & 3;
        cp16(sbase + 2 * STAGE_A + r * ROWB + kc * 16,
             Wh + (size_t)(colBase + r) * D_EMB + k0 + kc * 8);
    }
}

__global__ __launch_bounds__(256, 1)
void mma_gemm_bias_kernel(const __half* __restrict__ Ah,
                          const __half* __restrict__ Al,
                          const __half* __restrict__ Wh,
                          const float* __restrict__ bias,
                          float* __restrict__ C,
                          __half* __restrict__ H)
{
    extern __shared__ char smem[];
    const uint32_t sbase = smem_to_u32(smem);
    const int tid = threadIdx.x;
    const int wid = tid >> 5;
    const int lid = tid & 31;
    const int wm = wid & 1;
    const int wn = wid >> 1;
    const int rowBase = blockIdx.y * 128;
    const int colBase = blockIdx.x * 256;

    float c[4][8][4];
#pragma unroll
    for (int i = 0; i < 4; i++)
#pragma unroll
        for (int j = 0; j < 8; j++)
#pragma unroll
            for (int q = 0; q < 4; q++) c[i][j][q] = 0.f;

    const uint32_t a_lane = (uint32_t)((wm * 64 + (lid & 15)) * ROWB + (lid >> 4) * 16);
    const int bmi = lid >> 3, bwi = lid & 7;
    const uint32_t b_lane = (uint32_t)((wn * 64 + ((bmi >> 1) << 3) + bwi) * ROWB
                                       + (bmi & 1) * 16);

    load_stage(Ah, Al, Wh, rowBase, colBase, 0, sbase, tid);
    CP_COMMIT();

    for (int ch = 0; ch < 32; ch++) {
        CP_WAIT_ALL();
        __syncthreads();
        if (ch + 1 < 32) {
            load_stage(Ah, Al, Wh, rowBase, colBase, (ch + 1) * 32,
                       sbase + ((ch + 1) & 1) * STAGE_TOTAL, tid);
            CP_COMMIT();
        }
        const uint32_t sA = sbase + (ch & 1) * STAGE_TOTAL;
        const uint32_t sB = sA + 2 * STAGE_A;

#pragma unroll
        for (int kk = 0; kk < 2; kk++) {
            const uint32_t kb = kk * 32;
            uint32_t af[4][4], bh[4][4];
#pragma unroll
            for (int mt = 0; mt < 4; mt++)
                LDSM_X4(af[mt][0], af[mt][1], af[mt][2], af[mt][3],
                        sA + a_lane + mt * (16 * ROWB) + kb);
#pragma unroll
            for (int np = 0; np < 4; np++)
                LDSM_X4(bh[np][0], bh[np][1], bh[np][2], bh[np][3],
                        sB + b_lane + np * (16 * ROWB) + kb);
#pragma unroll
            for (int mt = 0; mt < 4; mt++)
#pragma unroll
                for (int np = 0; np < 4; np++) {
                    MMAHX(c[mt][np * 2],     af[mt], bh[np][0], bh[np][1]);
                    MMAHX(c[mt][np * 2 + 1], af[mt], bh[np][2], bh[np][3]);
                }
#pragma unroll
            for (int mt = 0; mt < 4; mt++)
                LDSM_X4(af[mt][0], af[mt][1], af[mt][2], af[mt][3],
                        sA + STAGE_A + a_lane + mt * (16 * ROWB) + kb);
#pragma unroll
            for (int mt = 0; mt < 4; mt++)
#pragma unroll
                for (int np = 0; np < 4; np++) {
                    MMAHX(c[mt][np * 2],     af[mt], bh[np][0], bh[np][1]);
                    MMAHX(c[mt][np * 2 + 1], af[mt], bh[np][2], bh[np][3]);
                }
        }
    }

    const int r0 = rowBase + wm * 64 + (lid >> 2);
    const int c0 = colBase + wn * 64 + (lid & 3) * 2;
#pragma unroll
    for (int mt = 0; mt < 4; mt++) {
#pragma unroll
        for (int nt = 0; nt < 8; nt++) {
            const int row = r0 + mt * 16;
            const int col = c0 + nt * 8;
            float2 bv = *(const float2*)&bias[col];
            float v00 = c[mt][nt][0] + bv.x, v01 = c[mt][nt][1] + bv.y;
            float v10 = c[mt][nt][2] + bv.x, v11 = c[mt][nt][3] + bv.y;
            if (C) {
                *(float2*)&C[(size_t)row * D_EMB + col] = make_float2(v00, v01);
                *(float2*)&C[(size_t)(row + 8) * D_EMB + col] = make_float2(v10, v11);
            } else {
                *(__half2*)&H[(size_t)row * D_EMB + col] =
                    __half2(__float2half_rn(v00), __float2half_rn(v01));
                *(__half2*)&H[(size_t)(row + 8) * D_EMB + col] =
                    __half2(__float2half_rn(v10), __float2half_rn(v11));
            }
        }
    }
}

// ---------------------------------------------------------------------------
// Tensor-core flash attention, single-term fp16 QK and PV.
//   CTA processes TWO q-tiles (15-bx, bx) -> 256 equal-work CTAs, one wave.
//   8 warps x 16 rows; KV blocks of 64, 2-stage cp.async.
// ---------------------------------------------------------------------------
#define AROW     144
#define SM_Q     0
#define SM_KV    18432
#define KV_STAGE 18432
#define V_OFF    9216
#define ATT_SMEM (SM_KV + 2 * KV_STAGE)   // 55296

__global__ __launch_bounds__(256, 2)
void attn_mma_kernel(const __half* __restrict__ Q, const __half* __restrict__ K,
                     const __half* __restrict__ V,
                     __half* __restrict__ Oh, __half* __restrict__ Ol)
{
    extern __shared__ char sm[];
    const uint32_t sb = smem_to_u32(sm);
    const int tid = threadIdx.x, wid = tid >> 5, lid = tid & 31;
    const int bx = blockIdx.x;              // 0..7
    const int h = blockIdx.y, b = blockIdx.z;
    const int colH = h * DH;

    const uint32_t a_off = (uint32_t)((wid * 16 + (lid & 15)) * AROW + (lid >> 4) * 16);
    const int bmi = lid >> 3;
    const uint32_t k_off = (uint32_t)((((bmi >> 1) << 3) + (lid & 7)) * AROW + (bmi & 1) * 16);
    const uint32_t v_off = (uint32_t)((((bmi & 1) << 3) + (lid & 7)) * AROW + (lid >> 4) * 16);

#pragma unroll 1
    for (int t2 = 0; t2 < 2; t2++) {
        const int qt = t2 ? bx : 15 - bx;    // pair sums to 15: uniform work
        const size_t qRow0 = (size_t)b * S_LEN + (size_t)qt * 128;
        const int kbmax = 2 * qt + 1;

        __syncthreads();                     // smem free from previous tile

        // load Q tile + KV block 0 (one group)
#pragma unroll
        for (int t = 0; t < 4; t++) {
            int idx = tid + t * 256;
            int r = (idx >> 3) & 127, cc = idx & 7;
            cp16(sb + SM_Q + r * AROW + cc * 16,
                 Q + (qRow0 + r) * D_EMB + colH + cc * 8);
        }
        {
            size_t kRow0 = (size_t)b * S_LEN;
#pragma unroll
            for (int t = 0; t < 4; t++) {
                int idx = tid + t * 256;
                int tile = idx >> 9;         // 0=K 1=V
                int r = (idx >> 3) & 63, cc = idx & 7;
                const __half* src = (tile ? V : K) + (kRow0 + r) * D_EMB + colH + cc * 8;
                cp16(sb + SM_KV + tile * 9216 + r * AROW + cc * 16, src);
            }
        }
        CP_COMMIT();

        float m0 = -1e30f, m1 = -1e30f, l0 = 0.f, l1 = 0.f;
        float o[8][4];
#pragma unroll
        for (int j = 0; j < 8; j++)
#pragma unroll
            for (int q = 0; q < 4; q++) o[j][q] = 0.f;

        for (int kb = 0; kb <= kbmax; kb++) {
            __syncthreads();
            if (kb < kbmax) {
                size_t kRow0 = (size_t)b * S_LEN + (size_t)(kb + 1) * 64;
                uint32_t base = sb + SM_KV + ((kb + 1) & 1) * KV_STAGE;
#pragma unroll
                for (int t = 0; t < 4; t++) {
                    int idx = tid + t * 256;
                    int tile = idx >> 9;
                    int r = (idx >> 3) & 63, cc = idx & 7;
                    const __half* src = (tile ? V : K) + (kRow0 + r) * D_EMB + colH + cc * 8;
                    cp16(base + tile * 9216 + r * AROW + cc * 16, src);
                }
                CP_COMMIT();
                CP_WAIT_1();
            } else {
                CP_WAIT_ALL();
            }
            __syncthreads();

            const uint32_t skv = sb + SM_KV + (kb & 1) * KV_STAGE;

            // ---- scores: Q @ K^T (single fp16 term) ----
            float c[8][4];
#pragma unroll
            for (int j = 0; j < 8; j++)
#pragma unroll
                for (int q = 0; q < 4; q++) c[j][q] = 0.f;

#pragma unroll
            for (int ks = 0; ks < 4; ks++) {
                uint32_t a0, a1, a2, a3;
                LDSM_X4(a0, a1, a2, a3, sb + SM_Q + a_off + ks * 32);
#pragma unroll
                for (int np = 0; np < 4; np++) {
                    uint32_t b0, b1, b2, b3;
                    LDSM_X4(b0, b1, b2, b3, skv + k_off + np * (16 * AROW) + ks * 32);
                    MMAH(c[2 * np],     a0, a1, a2, a3, b0, b1);
                    MMAH(c[2 * np + 1], a0, a1, a2, a3, b2, b3);
                }
            }

            // ---- scale + causal mask ----
            const int rA = qt * 128 + wid * 16 + (lid >> 2);
            const bool needMask = (kb * 64 + 63) > (qt * 128 + wid * 16);
#pragma unroll
            for (int j = 0; j < 8; j++) {
                int colg = kb * 64 + j * 8 + (lid & 3) * 2;
#pragma unroll
                for (int q = 0; q < 4; q++) {
                    float s = c[j][q] * 0.03125f;
                    if (needMask) {
                        int cg = colg + (q & 1);
                        int rr = rA + ((q >= 2) ? 8 : 0);
                        if (cg > rr) s = -1e30f;
                    }
                    c[j][q] = s;
                }
            }

            // ---- online softmax ----
            float mxA = -1e30f, mxB = -1e30f;
#pragma unroll
            for (int j = 0; j < 8; j++) {
                mxA = fmaxf(mxA, fmaxf(c[j][0], c[j][1]));
                mxB = fmaxf(mxB, fmaxf(c[j][2], c[j][3]));
            }
            mxA = fmaxf(mxA, __shfl_xor_sync(0xffffffffu, mxA, 1));
            mxA = fmaxf(mxA, __shfl_xor_sync(0xffffffffu, mxA, 2));
            mxB = fmaxf(mxB, __shfl_xor_sync(0xffffffffu, mxB, 1));
            mxB = fmaxf(mxB, __shfl_xor_sync(0xffffffffu, mxB, 2));
            float mnA = fmaxf(m0, mxA), mnB = fmaxf(m1, mxB);
            float alA = fast_exp(m0 - mnA), alB = fast_exp(m1 - mnB);
            m0 = mnA; m1 = mnB;

            uint32_t pA[8], pB[8];
            float sA = 0.f, sB = 0.f;
#pragma unroll
            for (int j = 0; j < 8; j++) {
                __half2 hA = __floats2half2_rn(fast_exp(c[j][0] - mnA),
                                               fast_exp(c[j][1] - mnA));
                __half2 hB = __floats2half2_rn(fast_exp(c[j][2] - mnB),
                                               fast_exp(c[j][3] - mnB));
                pA[j] = *reinterpret_cast<uint32_t*>(&hA);
                pB[j] = *reinterpret_cast<uint32_t*>(&hB);
                sA += __low2float(hA) + __high2float(hA);
                sB += __low2float(hB) + __high2float(hB);
            }
            sA += __shfl_xor_sync(0xffffffffu, sA, 1);
            sA += __shfl_xor_sync(0xffffffffu, sA, 2);
            sB += __shfl_xor_sync(0xffffffffu, sB, 1);
            sB += __shfl_xor_sync(0xffffffffu, sB, 2);
            l0 = l0 * alA + sA;
            l1 = l1 * alB + sB;
#pragma unroll
            for (int j = 0; j < 8; j++) {
                o[j][0] *= alA; o[j][1] *= alA;
                o[j][2] *= alB; o[j][3] *= alB;
            }

            // ---- O += P @ V (single fp16 term) ----
#pragma unroll
            for (int ks = 0; ks < 4; ks++) {
                uint32_t a0 = pA[2 * ks], a1 = pB[2 * ks];
                uint32_t a2 = pA[2 * ks + 1], a3 = pB[2 * ks + 1];
#pragma unroll
                for (int np = 0; np < 4; np++) {
                    uint32_t b0, b1, b2, b3;
                    LDSM_X4T(b0, b1, b2, b3,
                             skv + V_OFF + v_off + ks * (16 * AROW) + np * 32);
                    MMAH(o[2 * np],     a0, a1, a2, a3, b0, b1);
                    MMAH(o[2 * np + 1], a0, a1, a2, a3, b2, b3);
                }
            }
        }

        // ---- normalize + write fp16 hi/lo (feeds Wo GEMM) ----
        const float invA = 1.f / l0, invB = 1.f / l1;
        const size_t rowA = qRow0 + wid * 16 + (lid >> 2);
#pragma unroll
        for (int j = 0; j < 8; j++) {
            int col = colH + j * 8 + (lid & 3) * 2;
            float v0 = o[j][0] * invA, v1 = o[j][1] * invA;
            float v2 = o[j][2] * invB, v3 = o[j][3] * invB;
            __half h0 = __float2half_rn(v0), h1 = __float2half_rn(v1);
            __half h2 = __float2half_rn(v2), h3 = __float2half_rn(v3);
            __half e0 = __float2half_rn(v0 - __half2float(h0));
            __half e1 = __float2half_rn(v1 - __half2float(h1));
            __half e2 = __float2half_rn(v2 - __half2float(h2));
            __half e3 = __float2half_rn(v3 - __half2float(h3));
            *(__half2*)&Oh[rowA * D_EMB + col] = __half2(h0, h1);
            *(__half2*)&Ol[rowA * D_EMB + col] = __half2(e0, e1);
            *(__half2*)&Oh[(rowA + 8) * D_EMB + col] = __half2(h2, h3);
            *(__half2*)&Ol[(rowA + 8) * D_EMB + col] = __half2(e2, e3);
        }
    }
}

// ---------------------------------------------------------------------------
extern "C" void kernel_launch(void* const* d_in, const int* in_sizes, int n_in,
                              void* d_out, int out_size)
{
    const float* x  = (const float*)d_in[0];
    const float* Wq = (const float*)d_in[1];
    const float* bq = (const float*)d_in[2];
    const float* Wk = (const float*)d_in[3];
    const float* bk = (const float*)d_in[4];
    const float* Wv = (const float*)d_in[5];
    const float* bv = (const float*)d_in[6];
    const float* Wo = (const float*)d_in[7];
    const float* bo = (const float*)d_in[8];
    float* out = (float*)d_out;

    __half *xh, *xl, *qh, *kh, *vh, *ah, *al;
    cudaGetSymbolAddress((void**)&xh, g_xh);
    cudaGetSymbolAddress((void**)&xl, g_xl);
    cudaGetSymbolAddress((void**)&qh, g_qh);
    cudaGetSymbolAddress((void**)&kh, g_kh);
    cudaGetSymbolAddress((void**)&vh, g_vh);
    cudaGetSymbolAddress((void**)&ah, g_ah);
    cudaGetSymbolAddress((void**)&al, g_al);
    __half *wq, *wk, *wv, *wo;
    cudaGetSymbolAddress((void**)&wq, g_wq);
    cudaGetSymbolAddress((void**)&wk, g_wk);
    cudaGetSymbolAddress((void**)&wv, g_wv);
    cudaGetSymbolAddress((void**)&wo, g_wo);

    cudaFuncSetAttribute(mma_gemm_bias_kernel,
                         cudaFuncAttributeMaxDynamicSharedMemorySize, GEMM_SMEM);
    cudaFuncSetAttribute(attn_mma_kernel,
                         cudaFuncAttributeMaxDynamicSharedMemorySize, ATT_SMEM);

    const int n4 = MROWS * D_EMB / 4;
    dim3 tgrid(32, 32), tblk(32, 8);
    dim3 ggrid(D_EMB / 256, MROWS / 128);       // (4, 32)

    split_fp16_kernel<<<(n4 + 255) / 256, 256>>>(x, xh, xl, n4);
    transpose_half_kernel<<<tgrid, tblk>>>(Wq, wq);
    transpose_half_kernel<<<tgrid, tblk>>>(Wk, wk);
    transpose_half_kernel<<<tgrid, tblk>>>(Wv, wv);
    transpose_half_kernel<<<tgrid, tblk>>>(Wo, wo);

    mma_gemm_bias_kernel<<<ggrid, 256, GEMM_SMEM>>>(xh, xl, wq, bq, nullptr, qh);
    mma_gemm_bias_kernel<<<ggrid, 256, GEMM_SMEM>>>(xh, xl, wk, bk, nullptr, kh);
    mma_gemm_bias_kernel<<<ggrid, 256, GEMM_SMEM>>>(xh, xl, wv, bv, nullptr, vh);

    attn_mma_kernel<<<dim3(8, NHEAD, BATCH), 256, ATT_SMEM>>>(qh, kh, vh, ah, al);

    mma_gemm_bias_kernel<<<ggrid, 256, GEMM_SMEM>>>(ah, al, wo, bo, out, nullptr);
}

// round 11
// speedup vs baseline: 3.3267x; 1.2362x over previous
#include <cuda_runtime.h>
#include <cuda_fp16.h>
#include <math.h>
#include <stdint.h>

#define S_LEN 2048
#define D_EMB 1024
#define NHEAD 16
#define DH    64
#define BATCH 2
#define MROWS (BATCH * S_LEN)   // 4096

// ---------------- device scratch ----------------
__device__ __half g_xh[MROWS * D_EMB];
__device__ __half g_xl[MROWS * D_EMB];
__device__ __half g_qh[MROWS * D_EMB];
__device__ __half g_kh[MROWS * D_EMB];
__device__ __half g_vh[MROWS * D_EMB];
__device__ __half g_ah[MROWS * D_EMB];
__device__ __half g_al[MROWS * D_EMB];

__device__ __half g_wq[D_EMB * D_EMB];
__device__ __half g_wk[D_EMB * D_EMB];
__device__ __half g_wv[D_EMB * D_EMB];
__device__ __half g_wo[D_EMB * D_EMB];

// ---------------- helpers ----------------
__device__ __forceinline__ uint32_t smem_to_u32(const void* p) {
    uint32_t a;
    asm("{ .reg .u64 t; cvta.to.shared.u64 t, %1; cvt.u32.u64 %0, t; }"
        : "=r"(a) : "l"(p));
    return a;
}

__device__ __forceinline__ void cp16(uint32_t s, const void* g) {
    asm volatile("cp.async.cg.shared.global [%0], [%1], 16;" :: "r"(s), "l"(g));
}
#define CP_COMMIT()  asm volatile("cp.async.commit_group;" ::: "memory")
#define CP_WAIT_ALL() asm volatile("cp.async.wait_group 0;" ::: "memory")
#define CP_WAIT_1()  asm volatile("cp.async.wait_group 1;" ::: "memory")

#define LDSM_X4(r0, r1, r2, r3, addr) \
    asm volatile("ldmatrix.sync.aligned.m8n8.x4.shared.b16 {%0,%1,%2,%3}, [%4];" \
        : "=r"(r0), "=r"(r1), "=r"(r2), "=r"(r3) : "r"(addr))

#define LDSM_X4T(r0, r1, r2, r3, addr) \
    asm volatile("ldmatrix.sync.aligned.m8n8.x4.trans.shared.b16 {%0,%1,%2,%3}, [%4];" \
        : "=r"(r0), "=r"(r1), "=r"(r2), "=r"(r3) : "r"(addr))

#define MMAHX(c, a, b0, b1) \
    asm volatile("mma.sync.aligned.m16n8k16.row.col.f32.f16.f16.f32 " \
        "{%0,%1,%2,%3}, {%4,%5,%6,%7}, {%8,%9}, {%0,%1,%2,%3};" \
        : "+f"((c)[0]), "+f"((c)[1]), "+f"((c)[2]), "+f"((c)[3]) \
        : "r"((a)[0]), "r"((a)[1]), "r"((a)[2]), "r"((a)[3]), "r"(b0), "r"(b1))

#define MMAH(c, a0, a1, a2, a3, b0, b1) \
    asm volatile("mma.sync.aligned.m16n8k16.row.col.f32.f16.f16.f32 " \
        "{%0,%1,%2,%3}, {%4,%5,%6,%7}, {%8,%9}, {%0,%1,%2,%3};" \
        : "+f"((c)[0]), "+f"((c)[1]), "+f"((c)[2]), "+f"((c)[3]) \
        : "r"(a0), "r"(a1), "r"(a2), "r"(a3), "r"(b0), "r"(b1))

// FMA-pipe exp: exp(x) = 2^(x*log2e), deg-5 on [-0.5,0.5]; valid x <= 0.
__device__ __forceinline__ float fast_exp(float x) {
    x = fmaxf(x, -87.0f);
    float y = fmaf(x, 1.4426950408889634f, 12582912.0f);
    int   e = __float_as_int(y) - 0x4B400000;
    float i = y - 12582912.0f;
    float f = fmaf(x, 1.4426950408889634f, -i);
    float p =           1.3333558e-3f;
    p = fmaf(p, f, 9.6181291e-3f);
    p = fmaf(p, f, 5.5504109e-2f);
    p = fmaf(p, f, 2.4022651e-1f);
    p = fmaf(p, f, 6.9314718e-1f);
    p = fmaf(p, f, 1.0f);
    return p * __int_as_float((127 + e) << 23);
}

// ---------------------------------------------------------------------------
// split fp32 -> fp16 hi/lo
// ---------------------------------------------------------------------------
__global__ __launch_bounds__(256)
void split_fp16_kernel(const float* __restrict__ in,
                       __half* __restrict__ hi, __half* __restrict__ lo, int n4)
{
    int idx = blockIdx.x * 256 + threadIdx.x;
    if (idx >= n4) return;
    float4 v = *(const float4*)(in + (size_t)idx * 4);
    __half h0 = __float2half_rn(v.x), h1 = __float2half_rn(v.y);
    __half h2 = __float2half_rn(v.z), h3 = __float2half_rn(v.w);
    __half l0 = __float2half_rn(v.x - __half2float(h0));
    __half l1 = __float2half_rn(v.y - __half2float(h1));
    __half l2 = __float2half_rn(v.z - __half2float(h2));
    __half l3 = __float2half_rn(v.w - __half2float(h3));
    __half2* hp = (__half2*)(hi + (size_t)idx * 4);
    __half2* lp = (__half2*)(lo + (size_t)idx * 4);
    hp[0] = __half2(h0, h1); hp[1] = __half2(h2, h3);
    lp[0] = __half2(l0, l1); lp[1] = __half2(l2, l3);
}

// ---------------------------------------------------------------------------
// fused transpose of all 4 weights:  T[n,k] = (half)W[k,n]; z picks matrix
// ---------------------------------------------------------------------------
__global__ __launch_bounds__(256)
void transpose_half4_kernel(const float* __restrict__ W0, const float* __restrict__ W1,
                            const float* __restrict__ W2, const float* __restrict__ W3,
                            __half* __restrict__ T0, __half* __restrict__ T1,
                            __half* __restrict__ T2, __half* __restrict__ T3)
{
    const float* W = (blockIdx.z == 0) ? W0 : (blockIdx.z == 1) ? W1
                     : (blockIdx.z == 2) ? W2 : W3;
    __half* T = (blockIdx.z == 0) ? T0 : (blockIdx.z == 1) ? T1
                : (blockIdx.z == 2) ? T2 : T3;
    __shared__ float t[32][33];
    const int tx = threadIdx.x, ty = threadIdx.y;  // 32 x 8
    const int n0 = blockIdx.x * 32;
    const int k0 = blockIdx.y * 32;
#pragma unroll
    for (int i = 0; i < 4; i++)
        t[ty + i * 8][tx] = W[(size_t)(k0 + ty + i * 8) * D_EMB + n0 + tx];
    __syncthreads();
#pragma unroll
    for (int i = 0; i < 4; i++) {
        int n = n0 + ty + i * 8;
        int k = k0 + tx;
        T[(size_t)n * D_EMB + k] = __float2half_rn(t[tx][ty + i * 8]);
    }
}

// ---------------------------------------------------------------------------
// fp16 GEMM: C = (Ah [+ Al]) @ W^T + bias.  TWO_TERM templated.
//   CTA 128x256, 8 warps (2x4), warp tile 64x64, BK=32, 2-stage cp.async.
// ---------------------------------------------------------------------------
#define ROWB      80
#define STAGE_A   (128 * ROWB)             // 10240
#define STAGE_B   (256 * ROWB)             // 20480
#define STAGE_TOTAL (2 * STAGE_A + STAGE_B)  // 40960
#define GEMM_SMEM (2 * STAGE_TOTAL)        // 81920

template<bool TWO_TERM>
__device__ __forceinline__ void load_stage(
    const __half* __restrict__ Ah, const __half* __restrict__ Al,
    const __half* __restrict__ Wh,
    int rowBase, int colBase, int k0, uint32_t sbase, int tid)
{
#pragma unroll
    for (int i = 0; i < 2; i++) {
        int c = tid * 2 + i;
        int r = c >> 2, kc = c & 3;
        size_t goff = (size_t)(rowBase + r) * D_EMB + k0 + kc * 8;
        uint32_t soff = r * ROWB + kc * 16;
        cp16(sbase + soff, Ah + goff);
        if (TWO_TERM) cp16(sbase + STAGE_A + soff, Al + goff);
    }
#pragma unroll
    for (int i = 0; i < 4; i++) {
        int c = tid * 4 + i;
        int r = c >> 2, kc = c & 3;
        cp16(sbase + 2 * STAGE_A + r * ROWB + kc * 16,
             Wh + (size_t)(colBase + r) * D_EMB + k0 + kc * 8);
    }
}

template<bool TWO_TERM>
__global__ __launch_bounds__(256, 1)
void mma_gemm_bias_kernel(const __half* __restrict__ Ah,
                          const __half* __restrict__ Al,
                          const __half* __restrict__ Wh,
                          const float* __restrict__ bias,
                          float* __restrict__ C,
                          __half* __restrict__ H)
{
    extern __shared__ char smem[];
    const uint32_t sbase = smem_to_u32(smem);
    const int tid = threadIdx.x;
    const int wid = tid >> 5;
    const int lid = tid & 31;
    const int wm = wid & 1;
    const int wn = wid >> 1;
    const int rowBase = blockIdx.y * 128;
    const int colBase = blockIdx.x * 256;

    float c[4][8][4];
#pragma unroll
    for (int i = 0; i < 4; i++)
#pragma unroll
        for (int j = 0; j < 8; j++)
#pragma unroll
            for (int q = 0; q < 4; q++) c[i][j][q] = 0.f;

    const uint32_t a_lane = (uint32_t)((wm * 64 + (lid & 15)) * ROWB + (lid >> 4) * 16);
    const int bmi = lid >> 3, bwi = lid & 7;
    const uint32_t b_lane = (uint32_t)((wn * 64 + ((bmi >> 1) << 3) + bwi) * ROWB
                                       + (bmi & 1) * 16);

    load_stage<TWO_TERM>(Ah, Al, Wh, rowBase, colBase, 0, sbase, tid);
    CP_COMMIT();

    for (int ch = 0; ch < 32; ch++) {
        CP_WAIT_ALL();
        __syncthreads();
        if (ch + 1 < 32) {
            load_stage<TWO_TERM>(Ah, Al, Wh, rowBase, colBase, (ch + 1) * 32,
                                 sbase + ((ch + 1) & 1) * STAGE_TOTAL, tid);
            CP_COMMIT();
        }
        const uint32_t sA = sbase + (ch & 1) * STAGE_TOTAL;
        const uint32_t sB = sA + 2 * STAGE_A;

#pragma unroll
        for (int kk = 0; kk < 2; kk++) {
            const uint32_t kb = kk * 32;
            uint32_t af[4][4], bh[4][4];
#pragma unroll
            for (int mt = 0; mt < 4; mt++)
                LDSM_X4(af[mt][0], af[mt][1], af[mt][2], af[mt][3],
                        sA + a_lane + mt * (16 * ROWB) + kb);
#pragma unroll
            for (int np = 0; np < 4; np++)
                LDSM_X4(bh[np][0], bh[np][1], bh[np][2], bh[np][3],
                        sB + b_lane + np * (16 * ROWB) + kb);
#pragma unroll
            for (int mt = 0; mt < 4; mt++)
#pragma unroll
                for (int np = 0; np < 4; np++) {
                    MMAHX(c[mt][np * 2],     af[mt], bh[np][0], bh[np][1]);
                    MMAHX(c[mt][np * 2 + 1], af[mt], bh[np][2], bh[np][3]);
                }
            if (TWO_TERM) {
#pragma unroll
                for (int mt = 0; mt < 4; mt++)
                    LDSM_X4(af[mt][0], af[mt][1], af[mt][2], af[mt][3],
                            sA + STAGE_A + a_lane + mt * (16 * ROWB) + kb);
#pragma unroll
                for (int mt = 0; mt < 4; mt++)
#pragma unroll
                    for (int np = 0; np < 4; np++) {
                        MMAHX(c[mt][np * 2],     af[mt], bh[np][0], bh[np][1]);
                        MMAHX(c[mt][np * 2 + 1], af[mt], bh[np][2], bh[np][3]);
                    }
            }
        }
    }

    const int r0 = rowBase + wm * 64 + (lid >> 2);
    const int c0 = colBase + wn * 64 + (lid & 3) * 2;
#pragma unroll
    for (int mt = 0; mt < 4; mt++) {
#pragma unroll
        for (int nt = 0; nt < 8; nt++) {
            const int row = r0 + mt * 16;
            const int col = c0 + nt * 8;
            float2 bv = *(const float2*)&bias[col];
            float v00 = c[mt][nt][0] + bv.x, v01 = c[mt][nt][1] + bv.y;
            float v10 = c[mt][nt][2] + bv.x, v11 = c[mt][nt][3] + bv.y;
            if (C) {
                *(float2*)&C[(size_t)row * D_EMB + col] = make_float2(v00, v01);
                *(float2*)&C[(size_t)(row + 8) * D_EMB + col] = make_float2(v10, v11);
            } else {
                *(__half2*)&H[(size_t)row * D_EMB + col] =
                    __half2(__float2half_rn(v00), __float2half_rn(v01));
                *(__half2*)&H[(size_t)(row + 8) * D_EMB + col] =
                    __half2(__float2half_rn(v10), __float2half_rn(v11));
            }
        }
    }
}

// ---------------------------------------------------------------------------
// Tensor-core flash attention, single-term fp16 QK and PV.
//   CTA processes TWO q-tiles (15-bx, bx) -> 256 equal-work CTAs, one wave.
// ---------------------------------------------------------------------------
#define AROW     144
#define SM_Q     0
#define SM_KV    18432
#define KV_STAGE 18432
#define V_OFF    9216
#define ATT_SMEM (SM_KV + 2 * KV_STAGE)   // 55296

__global__ __launch_bounds__(256, 2)
void attn_mma_kernel(const __half* __restrict__ Q, const __half* __restrict__ K,
                     const __half* __restrict__ V,
                     __half* __restrict__ Oh, __half* __restrict__ Ol)
{
    extern __shared__ char sm[];
    const uint32_t sb = smem_to_u32(sm);
    const int tid = threadIdx.x, wid = tid >> 5, lid = tid & 31;
    const int bx = blockIdx.x;              // 0..7
    const int h = blockIdx.y, b = blockIdx.z;
    const int colH = h * DH;

    const uint32_t a_off = (uint32_t)((wid * 16 + (lid & 15)) * AROW + (lid >> 4) * 16);
    const int bmi = lid >> 3;
    const uint32_t k_off = (uint32_t)((((bmi >> 1) << 3) + (lid & 7)) * AROW + (bmi & 1) * 16);
    const uint32_t v_off = (uint32_t)((((bmi & 1) << 3) + (lid & 7)) * AROW + (lid >> 4) * 16);

#pragma unroll 1
    for (int t2 = 0; t2 < 2; t2++) {
        const int qt = t2 ? bx : 15 - bx;
        const size_t qRow0 = (size_t)b * S_LEN + (size_t)qt * 128;
        const int kbmax = 2 * qt + 1;

        __syncthreads();

#pragma unroll
        for (int t = 0; t < 4; t++) {
            int idx = tid + t * 256;
            int r = (idx >> 3) & 127, cc = idx & 7;
            cp16(sb + SM_Q + r * AROW + cc * 16,
                 Q + (qRow0 + r) * D_EMB + colH + cc * 8);
        }
        {
            size_t kRow0 = (size_t)b * S_LEN;
#pragma unroll
            for (int t = 0; t < 4; t++) {
                int idx = tid + t * 256;
                int tile = idx >> 9;
                int r = (idx >> 3) & 63, cc = idx & 7;
                const __half* src = (tile ? V : K) + (kRow0 + r) * D_EMB + colH + cc * 8;
                cp16(sb + SM_KV + tile * 9216 + r * AROW + cc * 16, src);
            }
        }
        CP_COMMIT();

        float m0 = -1e30f, m1 = -1e30f, l0 = 0.f, l1 = 0.f;
        float o[8][4];
#pragma unroll
        for (int j = 0; j < 8; j++)
#pragma unroll
            for (int q = 0; q < 4; q++) o[j][q] = 0.f;

        for (int kb = 0; kb <= kbmax; kb++) {
            __syncthreads();
            if (kb < kbmax) {
                size_t kRow0 = (size_t)b * S_LEN + (size_t)(kb + 1) * 64;
                uint32_t base = sb + SM_KV + ((kb + 1) & 1) * KV_STAGE;
#pragma unroll
                for (int t = 0; t < 4; t++) {
                    int idx = tid + t * 256;
                    int tile = idx >> 9;
                    int r = (idx >> 3) & 63, cc = idx & 7;
                    const __half* src = (tile ? V : K) + (kRow0 + r) * D_EMB + colH + cc * 8;
                    cp16(base + tile * 9216 + r * AROW + cc * 16, src);
                }
                CP_COMMIT();
                CP_WAIT_1();
            } else {
                CP_WAIT_ALL();
            }
            __syncthreads();

            const uint32_t skv = sb + SM_KV + (kb & 1) * KV_STAGE;

            float c[8][4];
#pragma unroll
            for (int j = 0; j < 8; j++)
#pragma unroll
                for (int q = 0; q < 4; q++) c[j][q] = 0.f;

#pragma unroll
            for (int ks = 0; ks < 4; ks++) {
                uint32_t a0, a1, a2, a3;
                LDSM_X4(a0, a1, a2, a3, sb + SM_Q + a_off + ks * 32);
#pragma unroll
                for (int np = 0; np < 4; np++) {
                    uint32_t b0, b1, b2, b3;
                    LDSM_X4(b0, b1, b2, b3, skv + k_off + np * (16 * AROW) + ks * 32);
                    MMAH(c[2 * np],     a0, a1, a2, a3, b0, b1);
                    MMAH(c[2 * np + 1], a0, a1, a2, a3, b2, b3);
                }
            }

            const int rA = qt * 128 + wid * 16 + (lid >> 2);
            const bool needMask = (kb * 64 + 63) > (qt * 128 + wid * 16);
#pragma unroll
            for (int j = 0; j < 8; j++) {
                int colg = kb * 64 + j * 8 + (lid & 3) * 2;
#pragma unroll
                for (int q = 0; q < 4; q++) {
                    float s = c[j][q] * 0.03125f;
                    if (needMask) {
                        int cg = colg + (q & 1);
                        int rr = rA + ((q >= 2) ? 8 : 0);
                        if (cg > rr) s = -1e30f;
                    }
                    c[j][q] = s;
                }
            }

            float mxA = -1e30f, mxB = -1e30f;
#pragma unroll
            for (int j = 0; j < 8; j++) {
                mxA = fmaxf(mxA, fmaxf(c[j][0], c[j][1]));
                mxB = fmaxf(mxB, fmaxf(c[j][2], c[j][3]));
            }
            mxA = fmaxf(mxA, __shfl_xor_sync(0xffffffffu, mxA, 1));
            mxA = fmaxf(mxA, __shfl_xor_sync(0xffffffffu, mxA, 2));
            mxB = fmaxf(mxB, __shfl_xor_sync(0xffffffffu, mxB, 1));
            mxB = fmaxf(mxB, __shfl_xor_sync(0xffffffffu, mxB, 2));
            float mnA = fmaxf(m0, mxA), mnB = fmaxf(m1, mxB);
            float alA = fast_exp(m0 - mnA), alB = fast_exp(m1 - mnB);
            m0 = mnA; m1 = mnB;

            uint32_t pA[8], pB[8];
            float sA = 0.f, sB = 0.f;
#pragma unroll
            for (int j = 0; j < 8; j++) {
                __half2 hA = __floats2half2_rn(fast_exp(c[j][0] - mnA),
                                               fast_exp(c[j][1] - mnA));
                __half2 hB = __floats2half2_rn(fast_exp(c[j][2] - mnB),
                                               fast_exp(c[j][3] - mnB));
                pA[j] = *reinterpret_cast<uint32_t*>(&hA);
                pB[j] = *reinterpret_cast<uint32_t*>(&hB);
                sA += __low2float(hA) + __high2float(hA);
                sB += __low2float(hB) + __high2float(hB);
            }
            sA += __shfl_xor_sync(0xffffffffu, sA, 1);
            sA += __shfl_xor_sync(0xffffffffu, sA, 2);
            sB += __shfl_xor_sync(0xffffffffu, sB, 1);
            sB += __shfl_xor_sync(0xffffffffu, sB, 2);
            l0 = l0 * alA + sA;
            l1 = l1 * alB + sB;
#pragma unroll
            for (int j = 0; j < 8; j++) {
                o[j][0] *= alA; o[j][1] *= alA;
                o[j][2] *= alB; o[j][3] *= alB;
            }

#pragma unroll
            for (int ks = 0; ks < 4; ks++) {
                uint32_t a0 = pA[2 * ks], a1 = pB[2 * ks];
                uint32_t a2 = pA[2 * ks + 1], a3 = pB[2 * ks + 1];
#pragma unroll
                for (int np = 0; np < 4; np++) {
                    uint32_t b0, b1, b2, b3;
                    LDSM_X4T(b0, b1, b2, b3,
                             skv + V_OFF + v_off + ks * (16 * AROW) + np * 32);
                    MMAH(o[2 * np],     a0, a1, a2, a3, b0, b1);
                    MMAH(o[2 * np + 1], a0, a1, a2, a3, b2, b3);
                }
            }
        }

        const float invA = 1.f / l0, invB = 1.f / l1;
        const size_t rowA = qRow0 + wid * 16 + (lid >> 2);
#pragma unroll
        for (int j = 0; j < 8; j++) {
            int col = colH + j * 8 + (lid & 3) * 2;
            float v0 = o[j][0] * invA, v1 = o[j][1] * invA;
            float v2 = o[j][2] * invB, v3 = o[j][3] * invB;
            __half h0 = __float2half_rn(v0), h1 = __float2half_rn(v1);
            __half h2 = __float2half_rn(v2), h3 = __float2half_rn(v3);
            __half e0 = __float2half_rn(v0 - __half2float(h0));
            __half e1 = __float2half_rn(v1 - __half2float(h1));
            __half e2 = __float2half_rn(v2 - __half2float(h2));
            __half e3 = __float2half_rn(v3 - __half2float(h3));
            *(__half2*)&Oh[rowA * D_EMB + col] = __half2(h0, h1);
            *(__half2*)&Ol[rowA * D_EMB + col] = __half2(e0, e1);
            *(__half2*)&Oh[(rowA + 8) * D_EMB + col] = __half2(h2, h3);
            *(__half2*)&Ol[(rowA + 8) * D_EMB + col] = __half2(e2, e3);
        }
    }
}

// ---------------------------------------------------------------------------
extern "C" void kernel_launch(void* const* d_in, const int* in_sizes, int n_in,
                              void* d_out, int out_size)
{
    const float* x  = (const float*)d_in[0];
    const float* Wq = (const float*)d_in[1];
    const float* bq = (const float*)d_in[2];
    const float* Wk = (const float*)d_in[3];
    const float* bk = (const float*)d_in[4];
    const float* Wv = (const float*)d_in[5];
    const float* bv = (const float*)d_in[6];
    const float* Wo = (const float*)d_in[7];
    const float* bo = (const float*)d_in[8];
    float* out = (float*)d_out;

    __half *xh, *xl, *qh, *kh, *vh, *ah, *al;
    cudaGetSymbolAddress((void**)&xh, g_xh);
    cudaGetSymbolAddress((void**)&xl, g_xl);
    cudaGetSymbolAddress((void**)&qh, g_qh);
    cudaGetSymbolAddress((void**)&kh, g_kh);
    cudaGetSymbolAddress((void**)&vh, g_vh);
    cudaGetSymbolAddress((void**)&ah, g_ah);
    cudaGetSymbolAddress((void**)&al, g_al);
    __half *wq, *wk, *wv, *wo;
    cudaGetSymbolAddress((void**)&wq, g_wq);
    cudaGetSymbolAddress((void**)&wk, g_wk);
    cudaGetSymbolAddress((void**)&wv, g_wv);
    cudaGetSymbolAddress((void**)&wo, g_wo);

    cudaFuncSetAttribute(mma_gemm_bias_kernel<false>,
                         cudaFuncAttributeMaxDynamicSharedMemorySize, GEMM_SMEM);
    cudaFuncSetAttribute(mma_gemm_bias_kernel<true>,
                         cudaFuncAttributeMaxDynamicSharedMemorySize, GEMM_SMEM);
    cudaFuncSetAttribute(attn_mma_kernel,
                         cudaFuncAttributeMaxDynamicSharedMemorySize, ATT_SMEM);

    const int n4 = MROWS * D_EMB / 4;
    dim3 tgrid(32, 32, 4), tblk(32, 8);
    dim3 ggrid(D_EMB / 256, MROWS / 128);       // (4, 32)

    split_fp16_kernel<<<(n4 + 255) / 256, 256>>>(x, xh, xl, n4);
    transpose_half4_kernel<<<tgrid, tblk>>>(Wq, Wk, Wv, Wo, wq, wk, wv, wo);

    // QKV: single-term fp16 A (softmax attenuates Q/K error; V adds ~2.8e-4)
    mma_gemm_bias_kernel<false><<<ggrid, 256, GEMM_SMEM>>>(xh, nullptr, wq, bq, nullptr, qh);
    mma_gemm_bias_kernel<false><<<ggrid, 256, GEMM_SMEM>>>(xh, nullptr, wk, bk, nullptr, kh);
    mma_gemm_bias_kernel<false><<<ggrid, 256, GEMM_SMEM>>>(xh, nullptr, wv, bv, nullptr, vh);

    attn_mma_kernel<<<dim3(8, NHEAD, BATCH), 256, ATT_SMEM>>>(qh, kh, vh, ah, al);

    // Wo: 2-term (attention output hi/lo) -> fp32 out
    mma_gemm_bias_kernel<true><<<ggrid, 256, GEMM_SMEM>>>(ah, al, wo, bo, out, nullptr);
}

// round 13
// speedup vs baseline: 3.4558x; 1.0388x over previous
#include <cuda_runtime.h>
#include <cuda_fp16.h>
#include <math.h>
#include <stdint.h>

#define S_LEN 2048
#define D_EMB 1024
#define NHEAD 16
#define DH    64
#define BATCH 2
#define MROWS (BATCH * S_LEN)   // 4096

// ---------------- device scratch ----------------
__device__ __half g_xh[MROWS * D_EMB];
__device__ __half g_xl[MROWS * D_EMB];
__device__ __half g_qh[MROWS * D_EMB];
__device__ __half g_kh[MROWS * D_EMB];
__device__ __half g_vh[MROWS * D_EMB];
__device__ __half g_ah[MROWS * D_EMB];
__device__ __half g_al[MROWS * D_EMB];

__device__ __half g_wq[D_EMB * D_EMB];
__device__ __half g_wk[D_EMB * D_EMB];
__device__ __half g_wv[D_EMB * D_EMB];
__device__ __half g_wo[D_EMB * D_EMB];

// ---------------- helpers ----------------
__device__ __forceinline__ uint32_t smem_to_u32(const void* p) {
    uint32_t a;
    asm("{ .reg .u64 t; cvta.to.shared.u64 t, %1; cvt.u32.u64 %0, t; }"
        : "=r"(a) : "l"(p));
    return a;
}

__device__ __forceinline__ void cp16(uint32_t s, const void* g) {
    asm volatile("cp.async.cg.shared.global [%0], [%1], 16;" :: "r"(s), "l"(g));
}
#define CP_COMMIT()   asm volatile("cp.async.commit_group;" ::: "memory")
#define CP_WAIT_ALL() asm volatile("cp.async.wait_group 0;" ::: "memory")
#define CP_WAIT_1()   asm volatile("cp.async.wait_group 1;" ::: "memory")

#define LDSM_X4(r0, r1, r2, r3, addr) \
    asm volatile("ldmatrix.sync.aligned.m8n8.x4.shared.b16 {%0,%1,%2,%3}, [%4];" \
        : "=r"(r0), "=r"(r1), "=r"(r2), "=r"(r3) : "r"(addr))

#define LDSM_X4T(r0, r1, r2, r3, addr) \
    asm volatile("ldmatrix.sync.aligned.m8n8.x4.trans.shared.b16 {%0,%1,%2,%3}, [%4];" \
        : "=r"(r0), "=r"(r1), "=r"(r2), "=r"(r3) : "r"(addr))

#define MMAHX(c, a, b0, b1) \
    asm volatile("mma.sync.aligned.m16n8k16.row.col.f32.f16.f16.f32 " \
        "{%0,%1,%2,%3}, {%4,%5,%6,%7}, {%8,%9}, {%0,%1,%2,%3};" \
        : "+f"((c)[0]), "+f"((c)[1]), "+f"((c)[2]), "+f"((c)[3]) \
        : "r"((a)[0]), "r"((a)[1]), "r"((a)[2]), "r"((a)[3]), "r"(b0), "r"(b1))

#define MMAH(c, a0, a1, a2, a3, b0, b1) \
    asm volatile("mma.sync.aligned.m16n8k16.row.col.f32.f16.f16.f32 " \
        "{%0,%1,%2,%3}, {%4,%5,%6,%7}, {%8,%9}, {%0,%1,%2,%3};" \
        : "+f"((c)[0]), "+f"((c)[1]), "+f"((c)[2]), "+f"((c)[3]) \
        : "r"(a0), "r"(a1), "r"(a2), "r"(a3), "r"(b0), "r"(b1))

// FMA-pipe exp: exp(x) = 2^(x*log2e), deg-5 on [-0.5,0.5]; valid x <= 0.
__device__ __forceinline__ float fast_exp(float x) {
    x = fmaxf(x, -87.0f);
    float y = fmaf(x, 1.4426950408889634f, 12582912.0f);
    int   e = __float_as_int(y) - 0x4B400000;
    float i = y - 12582912.0f;
    float f = fmaf(x, 1.4426950408889634f, -i);
    float p =           1.3333558e-3f;
    p = fmaf(p, f, 9.6181291e-3f);
    p = fmaf(p, f, 5.5504109e-2f);
    p = fmaf(p, f, 2.4022651e-1f);
    p = fmaf(p, f, 6.9314718e-1f);
    p = fmaf(p, f, 1.0f);
    return p * __int_as_float((127 + e) << 23);
}

// ---------------------------------------------------------------------------
// split fp32 -> fp16 hi/lo
// ---------------------------------------------------------------------------
__global__ __launch_bounds__(256)
void split_fp16_kernel(const float* __restrict__ in,
                       __half* __restrict__ hi, __half* __restrict__ lo, int n4)
{
    int idx = blockIdx.x * 256 + threadIdx.x;
    if (idx >= n4) return;
    float4 v = *(const float4*)(in + (size_t)idx * 4);
    __half h0 = __float2half_rn(v.x), h1 = __float2half_rn(v.y);
    __half h2 = __float2half_rn(v.z), h3 = __float2half_rn(v.w);
    __half l0 = __float2half_rn(v.x - __half2float(h0));
    __half l1 = __float2half_rn(v.y - __half2float(h1));
    __half l2 = __float2half_rn(v.z - __half2float(h2));
    __half l3 = __float2half_rn(v.w - __half2float(h3));
    __half2* hp = (__half2*)(hi + (size_t)idx * 4);
    __half2* lp = (__half2*)(lo + (size_t)idx * 4);
    hp[0] = __half2(h0, h1); hp[1] = __half2(h2, h3);
    lp[0] = __half2(l0, l1); lp[1] = __half2(l2, l3);
}

// ---------------------------------------------------------------------------
// fused transpose of all 4 weights:  T[n,k] = (half)W[k,n]; z picks matrix
// ---------------------------------------------------------------------------
__global__ __launch_bounds__(256)
void transpose_half4_kernel(const float* __restrict__ W0, const float* __restrict__ W1,
                            const float* __restrict__ W2, const float* __restrict__ W3,
                            __half* __restrict__ T0, __half* __restrict__ T1,
                            __half* __restrict__ T2, __half* __restrict__ T3)
{
    const float* W = (blockIdx.z == 0) ? W0 : (blockIdx.z == 1) ? W1
                     : (blockIdx.z == 2) ? W2 : W3;
    __half* T = (blockIdx.z == 0) ? T0 : (blockIdx.z == 1) ? T1
                : (blockIdx.z == 2) ? T2 : T3;
    __shared__ float t[32][33];
    const int tx = threadIdx.x, ty = threadIdx.y;  // 32 x 8
    const int n0 = blockIdx.x * 32;
    const int k0 = blockIdx.y * 32;
#pragma unroll
    for (int i = 0; i < 4; i++)
        t[ty + i * 8][tx] = W[(size_t)(k0 + ty + i * 8) * D_EMB + n0 + tx];
    __syncthreads();
#pragma unroll
    for (int i = 0; i < 4; i++) {
        int n = n0 + ty + i * 8;
        int k = k0 + tx;
        T[(size_t)n * D_EMB + k] = __float2half_rn(t[tx][ty + i * 8]);
    }
}

// ---------------------------------------------------------------------------
// fp16 GEMM: C = (Ah [+ Al]) @ W^T + bias.  TWO_TERM templated.
//   CTA 128x128, 8 warps (2x4), warp tile 64x32, BK=32, 3-stage cp.async,
//   2 CTAs/SM.  grid.z selects (W, bias, output) -> QKV fused in one launch.
// ---------------------------------------------------------------------------
#define ROWB   80
#define TILEB  (128 * ROWB)      // 10240 bytes per 128x32 fp16 tile

template<bool TWO_TERM>
__device__ __forceinline__ void load_stage(
    const __half* __restrict__ Ah, const __half* __restrict__ Al,
    const __half* __restrict__ Wh,
    int rowBase, int colBase, int k0, uint32_t sbase, int tid)
{
    constexpr uint32_t B_OFF = TWO_TERM ? 2 * TILEB : TILEB;
#pragma unroll
    for (int i = 0; i < 2; i++) {
        int c = tid * 2 + i;               // 0..511
        int r = c >> 2, kc = c & 3;
        size_t goff = (size_t)(rowBase + r) * D_EMB + k0 + kc * 8;
        uint32_t soff = r * ROWB + kc * 16;
        cp16(sbase + soff, Ah + goff);
        if (TWO_TERM) cp16(sbase + TILEB + soff, Al + goff);
        cp16(sbase + B_OFF + soff,
             Wh + (size_t)(colBase + r) * D_EMB + k0 + kc * 8);
    }
}

template<bool TWO_TERM>
__global__ __launch_bounds__(256, 2)
void mma_gemm_bias_kernel(const __half* __restrict__ Ah,
                          const __half* __restrict__ Al,
                          const __half* __restrict__ W0,
                          const __half* __restrict__ W1,
                          const __half* __restrict__ W2,
                          const float* __restrict__ b0,
                          const float* __restrict__ b1,
                          const float* __restrict__ b2,
                          __half* __restrict__ H0,
                          __half* __restrict__ H1,
                          __half* __restrict__ H2,
                          float* __restrict__ C)
{
    constexpr uint32_t B_OFF = TWO_TERM ? 2 * TILEB : TILEB;
    constexpr uint32_t STG   = TWO_TERM ? 3 * TILEB : 2 * TILEB;

    const __half* Wh  = (blockIdx.z == 0) ? W0 : (blockIdx.z == 1) ? W1 : W2;
    const float* bias = (blockIdx.z == 0) ? b0 : (blockIdx.z == 1) ? b1 : b2;
    __half* H         = (blockIdx.z == 0) ? H0 : (blockIdx.z == 1) ? H1 : H2;

    extern __shared__ char smem[];
    const uint32_t sbase = smem_to_u32(smem);
    const int tid = threadIdx.x;
    const int wid = tid >> 5;
    const int lid = tid & 31;
    const int wm = wid & 1;                 // 2 M warp-tiles of 64
    const int wn = wid >> 1;                // 4 N warp-tiles of 32
    const int rowBase = blockIdx.y * 128;
    const int colBase = blockIdx.x * 128;

    float c[4][4][4];
#pragma unroll
    for (int i = 0; i < 4; i++)
#pragma unroll
        for (int j = 0; j < 4; j++)
#pragma unroll
            for (int q = 0; q < 4; q++) c[i][j][q] = 0.f;

    const uint32_t a_lane = (uint32_t)((wm * 64 + (lid & 15)) * ROWB + (lid >> 4) * 16);
    const int bmi = lid >> 3, bwi = lid & 7;
    const uint32_t b_lane = (uint32_t)((wn * 32 + ((bmi >> 1) << 3) + bwi) * ROWB
                                       + (bmi & 1) * 16);

    load_stage<TWO_TERM>(Ah, Al, Wh, rowBase, colBase, 0, sbase, tid);
    CP_COMMIT();
    load_stage<TWO_TERM>(Ah, Al, Wh, rowBase, colBase, 32, sbase + STG, tid);
    CP_COMMIT();

    for (int ch = 0; ch < 32; ch++) {
        if (ch < 31) { CP_WAIT_1(); } else { CP_WAIT_ALL(); }
        __syncthreads();
        if (ch + 2 < 32) {
            load_stage<TWO_TERM>(Ah, Al, Wh, rowBase, colBase, (ch + 2) * 32,
                                 sbase + ((ch + 2) % 3) * STG, tid);
            CP_COMMIT();
        }
        const uint32_t sA = sbase + (ch % 3) * STG;
        const uint32_t sB = sA + B_OFF;

#pragma unroll
        for (int kk = 0; kk < 2; kk++) {
            const uint32_t kb = kk * 32;
            uint32_t af[4][4], bh[2][4];
#pragma unroll
            for (int mt = 0; mt < 4; mt++)
                LDSM_X4(af[mt][0], af[mt][1], af[mt][2], af[mt][3],
                        sA + a_lane + mt * (16 * ROWB) + kb);
#pragma unroll
            for (int np = 0; np < 2; np++)
                LDSM_X4(bh[np][0], bh[np][1], bh[np][2], bh[np][3],
                        sB + b_lane + np * (16 * ROWB) + kb);
#pragma unroll
            for (int mt = 0; mt < 4; mt++)
#pragma unroll
                for (int np = 0; np < 2; np++) {
                    MMAHX(c[mt][np * 2],     af[mt], bh[np][0], bh[np][1]);
                    MMAHX(c[mt][np * 2 + 1], af[mt], bh[np][2], bh[np][3]);
                }
            if (TWO_TERM) {
#pragma unroll
                for (int mt = 0; mt < 4; mt++)
                    LDSM_X4(af[mt][0], af[mt][1], af[mt][2], af[mt][3],
                            sA + TILEB + a_lane + mt * (16 * ROWB) + kb);
#pragma unroll
                for (int mt = 0; mt < 4; mt++)
#pragma unroll
                    for (int np = 0; np < 2; np++) {
                        MMAHX(c[mt][np * 2],     af[mt], bh[np][0], bh[np][1]);
                        MMAHX(c[mt][np * 2 + 1], af[mt], bh[np][2], bh[np][3]);
                    }
            }
        }
    }

    const int r0 = rowBase + wm * 64 + (lid >> 2);
    const int c0 = colBase + wn * 32 + (lid & 3) * 2;
#pragma unroll
    for (int mt = 0; mt < 4; mt++) {
#pragma unroll
        for (int nt = 0; nt < 4; nt++) {
            const int row = r0 + mt * 16;
            const int col = c0 + nt * 8;
            float2 bv = *(const float2*)&bias[col];
            float v00 = c[mt][nt][0] + bv.x, v01 = c[mt][nt][1] + bv.y;
            float v10 = c[mt][nt][2] + bv.x, v11 = c[mt][nt][3] + bv.y;
            if (C) {
                *(float2*)&C[(size_t)row * D_EMB + col] = make_float2(v00, v01);
                *(float2*)&C[(size_t)(row + 8) * D_EMB + col] = make_float2(v10, v11);
            } else {
                *(__half2*)&H[(size_t)row * D_EMB + col] =
                    __half2(__float2half_rn(v00), __float2half_rn(v01));
                *(__half2*)&H[(size_t)(row + 8) * D_EMB + col] =
                    __half2(__float2half_rn(v10), __float2half_rn(v11));
            }
        }
    }
}

#define GEMM_SMEM_1T (3 * 2 * TILEB)   // 61440
#define GEMM_SMEM_2T (3 * 3 * TILEB)   // 92160

// ---------------------------------------------------------------------------
// Tensor-core flash attention, single-term fp16 QK and PV.
//   CTA processes TWO q-tiles (15-bx, bx) -> 256 equal-work CTAs, one wave.
// ---------------------------------------------------------------------------
#define AROW     144
#define SM_Q     0
#define SM_KV    18432
#define KV_STAGE 18432
#define V_OFF    9216
#define ATT_SMEM (SM_KV + 2 * KV_STAGE)   // 55296

__global__ __launch_bounds__(256, 2)
void attn_mma_kernel(const __half* __restrict__ Q, const __half* __restrict__ K,
                     const __half* __restrict__ V,
                     __half* __restrict__ Oh, __half* __restrict__ Ol)
{
    extern __shared__ char sm[];
    const uint32_t sb = smem_to_u32(sm);
    const int tid = threadIdx.x, wid = tid >> 5, lid = tid & 31;
    const int bx = blockIdx.x;              // 0..7
    const int h = blockIdx.y, b = blockIdx.z;
    const int colH = h * DH;

    const uint32_t a_off = (uint32_t)((wid * 16 + (lid & 15)) * AROW + (lid >> 4) * 16);
    const int bmi = lid >> 3;
    const uint32_t k_off = (uint32_t)((((bmi >> 1) << 3) + (lid & 7)) * AROW + (bmi & 1) * 16);
    const uint32_t v_off = (uint32_t)((((bmi & 1) << 3) + (lid & 7)) * AROW + (lid >> 4) * 16);

#pragma unroll 1
    for (int t2 = 0; t2 < 2; t2++) {
        const int qt = t2 ? bx : 15 - bx;
        const size_t qRow0 = (size_t)b * S_LEN + (size_t)qt * 128;
        const int kbmax = 2 * qt + 1;

        __syncthreads();

#pragma unroll
        for (int t = 0; t < 4; t++) {
            int idx = tid + t * 256;
            int r = (idx >> 3) & 127, cc = idx & 7;
            cp16(sb + SM_Q + r * AROW + cc * 16,
                 Q + (qRow0 + r) * D_EMB + colH + cc * 8);
        }
        {
            size_t kRow0 = (size_t)b * S_LEN;
#pragma unroll
            for (int t = 0; t < 4; t++) {
                int idx = tid + t * 256;
                int tile = idx >> 9;
                int r = (idx >> 3) & 63, cc = idx & 7;
                const __half* src = (tile ? V : K) + (kRow0 + r) * D_EMB + colH + cc * 8;
                cp16(sb + SM_KV + tile * 9216 + r * AROW + cc * 16, src);
            }
        }
        CP_COMMIT();

        float m0 = -1e30f, m1 = -1e30f, l0 = 0.f, l1 = 0.f;
        float o[8][4];
#pragma unroll
        for (int j = 0; j < 8; j++)
#pragma unroll
            for (int q = 0; q < 4; q++) o[j][q] = 0.f;

        for (int kb = 0; kb <= kbmax; kb++) {
            __syncthreads();
            if (kb < kbmax) {
                size_t kRow0 = (size_t)b * S_LEN + (size_t)(kb + 1) * 64;
                uint32_t base = sb + SM_KV + ((kb + 1) & 1) * KV_STAGE;
#pragma unroll
                for (int t = 0; t < 4; t++) {
                    int idx = tid + t * 256;
                    int tile = idx >> 9;
                    int r = (idx >> 3) & 63, cc = idx & 7;
                    const __half* src = (tile ? V : K) + (kRow0 + r) * D_EMB + colH + cc * 8;
                    cp16(base + tile * 9216 + r * AROW + cc * 16, src);
                }
                CP_COMMIT();
                CP_WAIT_1();
            } else {
                CP_WAIT_ALL();
            }
            __syncthreads();

            const uint32_t skv = sb + SM_KV + (kb & 1) * KV_STAGE;

            float c[8][4];
#pragma unroll
            for (int j = 0; j < 8; j++)
#pragma unroll
                for (int q = 0; q < 4; q++) c[j][q] = 0.f;

#pragma unroll
            for (int ks = 0; ks < 4; ks++) {
                uint32_t a0, a1, a2, a3;
                LDSM_X4(a0, a1, a2, a3, sb + SM_Q + a_off + ks * 32);
#pragma unroll
                for (int np = 0; np < 4; np++) {
                    uint32_t b0, b1, b2, b3;
                    LDSM_X4(b0, b1, b2, b3, skv + k_off + np * (16 * AROW) + ks * 32);
                    MMAH(c[2 * np],     a0, a1, a2, a3, b0, b1);
                    MMAH(c[2 * np + 1], a0, a1, a2, a3, b2, b3);
                }
            }

            const int rA = qt * 128 + wid * 16 + (lid >> 2);
            const bool needMask = (kb * 64 + 63) > (qt * 128 + wid * 16);
#pragma unroll
            for (int j = 0; j < 8; j++) {
                int colg = kb * 64 + j * 8 + (lid & 3) * 2;
#pragma unroll
                for (int q = 0; q < 4; q++) {
                    float s = c[j][q] * 0.03125f;
                    if (needMask) {
                        int cg = colg + (q & 1);
                        int rr = rA + ((q >= 2) ? 8 : 0);
                        if (cg > rr) s = -1e30f;
                    }
                    c[j][q] = s;
                }
            }

            float mxA = -1e30f, mxB = -1e30f;
#pragma unroll
            for (int j = 0; j < 8; j++) {
                mxA = fmaxf(mxA, fmaxf(c[j][0], c[j][1]));
                mxB = fmaxf(mxB, fmaxf(c[j][2], c[j][3]));
            }
            mxA = fmaxf(mxA, __shfl_xor_sync(0xffffffffu, mxA, 1));
            mxA = fmaxf(mxA, __shfl_xor_sync(0xffffffffu, mxA, 2));
            mxB = fmaxf(mxB, __shfl_xor_sync(0xffffffffu, mxB, 1));
            mxB = fmaxf(mxB, __shfl_xor_sync(0xffffffffu, mxB, 2));
            float mnA = fmaxf(m0, mxA), mnB = fmaxf(m1, mxB);
            float alA = fast_exp(m0 - mnA), alB = fast_exp(m1 - mnB);
            m0 = mnA; m1 = mnB;

            uint32_t pA[8], pB[8];
            float sA = 0.f, sB = 0.f;
#pragma unroll
            for (int j = 0; j < 8; j++) {
                __half2 hA = __floats2half2_rn(fast_exp(c[j][0] - mnA),
                                               fast_exp(c[j][1] - mnA));
                __half2 hB = __floats2half2_rn(fast_exp(c[j][2] - mnB),
                                               fast_exp(c[j][3] - mnB));
                pA[j] = *reinterpret_cast<uint32_t*>(&hA);
                pB[j] = *reinterpret_cast<uint32_t*>(&hB);
                sA += __low2float(hA) + __high2float(hA);
                sB += __low2float(hB) + __high2float(hB);
            }
            sA += __shfl_xor_sync(0xffffffffu, sA, 1);
            sA += __shfl_xor_sync(0xffffffffu, sA, 2);
            sB += __shfl_xor_sync(0xffffffffu, sB, 1);
            sB += __shfl_xor_sync(0xffffffffu, sB, 2);
            l0 = l0 * alA + sA;
            l1 = l1 * alB + sB;
#pragma unroll
            for (int j = 0; j < 8; j++) {
                o[j][0] *= alA; o[j][1] *= alA;
                o[j][2] *= alB; o[j][3] *= alB;
            }

#pragma unroll
            for (int ks = 0; ks < 4; ks++) {
                uint32_t a0 = pA[2 * ks], a1 = pB[2 * ks];
                uint32_t a2 = pA[2 * ks + 1], a3 = pB[2 * ks + 1];
#pragma unroll
                for (int np = 0; np < 4; np++) {
                    uint32_t b0, b1, b2, b3;
                    LDSM_X4T(b0, b1, b2, b3,
                             skv + V_OFF + v_off + ks * (16 * AROW) + np * 32);
                    MMAH(o[2 * np],     a0, a1, a2, a3, b0, b1);
                    MMAH(o[2 * np + 1], a0, a1, a2, a3, b2, b3);
                }
            }
        }

        const float invA = 1.f / l0, invB = 1.f / l1;
        const size_t rowA = qRow0 + wid * 16 + (lid >> 2);
#pragma unroll
        for (int j = 0; j < 8; j++) {
            int col = colH + j * 8 + (lid & 3) * 2;
            float v0 = o[j][0] * invA, v1 = o[j][1] * invA;
            float v2 = o[j][2] * invB, v3 = o[j][3] * invB;
            __half h0 = __float2half_rn(v0), h1 = __float2half_rn(v1);
            __half h2 = __float2half_rn(v2), h3 = __float2half_rn(v3);
            __half e0 = __float2half_rn(v0 - __half2float(h0));
            __half e1 = __float2half_rn(v1 - __half2float(h1));
            __half e2 = __float2half_rn(v2 - __half2float(h2));
            __half e3 = __float2half_rn(v3 - __half2float(h3));
            *(__half2*)&Oh[rowA * D_EMB + col] = __half2(h0, h1);
            *(__half2*)&Ol[rowA * D_EMB + col] = __half2(e0, e1);
            *(__half2*)&Oh[(rowA + 8) * D_EMB + col] = __half2(h2, h3);
            *(__half2*)&Ol[(rowA + 8) * D_EMB + col] = __half2(e2, e3);
        }
    }
}

// ---------------------------------------------------------------------------
extern "C" void kernel_launch(void* const* d_in, const int* in_sizes, int n_in,
                              void* d_out, int out_size)
{
    const float* x  = (const float*)d_in[0];
    const float* Wq = (const float*)d_in[1];
    const float* bq = (const float*)d_in[2];
    const float* Wk = (const float*)d_in[3];
    const float* bk = (const float*)d_in[4];
    const float* Wv = (const float*)d_in[5];
    const float* bv = (const float*)d_in[6];
    const float* Wo = (const float*)d_in[7];
    const float* bo = (const float*)d_in[8];
    float* out = (float*)d_out;

    __half *xh, *xl, *qh, *kh, *vh, *ah, *al;
    cudaGetSymbolAddress((void**)&xh, g_xh);
    cudaGetSymbolAddress((void**)&xl, g_xl);
    cudaGetSymbolAddress((void**)&qh, g_qh);
    cudaGetSymbolAddress((void**)&kh, g_kh);
    cudaGetSymbolAddress((void**)&vh, g_vh);
    cudaGetSymbolAddress((void**)&ah, g_ah);
    cudaGetSymbolAddress((void**)&al, g_al);
    __half *wq, *wk, *wv, *wo;
    cudaGetSymbolAddress((void**)&wq, g_wq);
    cudaGetSymbolAddress((void**)&wk, g_wk);
    cudaGetSymbolAddress((void**)&wv, g_wv);
    cudaGetSymbolAddress((void**)&wo, g_wo);

    cudaFuncSetAttribute(mma_gemm_bias_kernel<false>,
                         cudaFuncAttributeMaxDynamicSharedMemorySize, GEMM_SMEM_1T);
    cudaFuncSetAttribute(mma_gemm_bias_kernel<true>,
                         cudaFuncAttributeMaxDynamicSharedMemorySize, GEMM_SMEM_2T);
    cudaFuncSetAttribute(attn_mma_kernel,
                         cudaFuncAttributeMaxDynamicSharedMemorySize, ATT_SMEM);

    const int n4 = MROWS * D_EMB / 4;
    dim3 tgrid(32, 32, 4), tblk(32, 8);

    split_fp16_kernel<<<(n4 + 255) / 256, 256>>>(x, xh, xl, n4);
    transpose_half4_kernel<<<tgrid, tblk>>>(Wq, Wk, Wv, Wo, wq, wk, wv, wo);

    // QKV fused: one launch, grid.z selects projection; single-term fp16 A
    mma_gemm_bias_kernel<false><<<dim3(8, 32, 3), 256, GEMM_SMEM_1T>>>(
        xh, nullptr, wq, wk, wv, bq, bk, bv, qh, kh, vh, nullptr);

    attn_mma_kernel<<<dim3(8, NHEAD, BATCH), 256, ATT_SMEM>>>(qh, kh, vh, ah, al);

    // Wo: 2-term (attention output hi/lo) -> fp32 out
    mma_gemm_bias_kernel<true><<<dim3(8, 32, 1), 256, GEMM_SMEM_2T>>>(
        ah, al, wo, wo, wo, bo, bo, bo, nullptr, nullptr, nullptr, out);
}